// round 3
// baseline (speedup 1.0000x reference)
#include <cuda_runtime.h>
#include <math.h>

#define BB   32
#define DD   768
#define NHD  12
#define HD   64
#define NMAX 197
#define LMAX 196
#define ATTN_SCALE 0.125f

// ---------------- scratch (device globals; no allocation allowed) ----------------
__device__ float g_t0[BB*NMAX*DD];
__device__ float g_t1[BB*NMAX*DD];
__device__ float g_ln[BB*NMAX*DD];
__device__ float g_qkv[BB*NMAX*2304];
__device__ float g_ao[BB*NMAX*DD];
__device__ float g_mlp[BB*NMAX*3072];
__device__ float g_pa[BB*LMAX*DD];
__device__ float g_pb[BB*LMAX*DD];
__device__ float g_glob[BB*384];
__device__ float g_score[BB*LMAX];
__device__ int   g_idx[BB*LMAX];
__device__ float g_cls[BB*DD];

__device__ __forceinline__ float gelu_f(float x) {
    return 0.5f * x * (1.f + erff(x * 0.70710678118654752440f));
}

// ---------------- im2col for patch embedding ----------------
__global__ void im2col_kernel(const float* __restrict__ x, float* __restrict__ p) {
    int i = blockIdx.x * blockDim.x + threadIdx.x;
    const int total = BB*LMAX*DD;
    if (i >= total) return;
    int c = i % DD;
    int r = i / DD;
    int b = r / LMAX;
    int l = r % LMAX;
    int gy = l / 14, gx = l % 14;
    int ch = c / 256, rem = c % 256, py = rem / 16, px = rem % 16;
    p[i] = x[(((size_t)b*3 + ch)*224 + gy*16 + py)*224 + gx*16 + px];
}

// assemble t = [cls | patches] + pos
__global__ void assemble_kernel(const float* __restrict__ pe, const float* __restrict__ cls,
                                const float* __restrict__ pos, float* __restrict__ t) {
    int i = blockIdx.x * blockDim.x + threadIdx.x;
    const int total = BB*NMAX*DD;
    if (i >= total) return;
    int d = i % DD;
    int n = (i / DD) % NMAX;
    int b = i / (DD*NMAX);
    float v = (n == 0) ? cls[d] : pe[((size_t)b*LMAX + (n-1))*DD + d];
    t[i] = v + pos[n*DD + d];
}

// ---------------- generic GEMM: C = act(A[M,K] @ W[N,K]^T + bias) (+resid) ------
// 64x64 tile, BK=16, 256 threads, 4x4 per thread
__global__ void gemm_kernel(const float* __restrict__ A, const float* __restrict__ W,
                            const float* __restrict__ bias, const float* __restrict__ resid,
                            float* __restrict__ C, int M, int N, int K, int act)
{
    __shared__ float As[16][65];
    __shared__ float Ws[16][65];
    int tx = threadIdx.x, ty = threadIdx.y;
    int tid = ty*16 + tx;
    int row0 = blockIdx.y*64, col0 = blockIdx.x*64;
    float acc[4][4] = {};
    for (int k0 = 0; k0 < K; k0 += 16) {
        #pragma unroll
        for (int i = 0; i < 4; i++) {
            int idx = tid + i*256;
            int r = idx >> 4;
            int c = idx & 15;
            int gr = row0 + r;
            As[c][r] = (gr < M) ? A[(size_t)gr*K + k0 + c] : 0.f;
            int wr = col0 + r;
            Ws[c][r] = (wr < N) ? W[(size_t)wr*K + k0 + c] : 0.f;
        }
        __syncthreads();
        #pragma unroll
        for (int kk = 0; kk < 16; kk++) {
            float a[4], bb[4];
            #pragma unroll
            for (int i = 0; i < 4; i++) a[i] = As[kk][ty*4+i];
            #pragma unroll
            for (int j = 0; j < 4; j++) bb[j] = Ws[kk][tx*4+j];
            #pragma unroll
            for (int i = 0; i < 4; i++)
                #pragma unroll
                for (int j = 0; j < 4; j++)
                    acc[i][j] = fmaf(a[i], bb[j], acc[i][j]);
        }
        __syncthreads();
    }
    #pragma unroll
    for (int i = 0; i < 4; i++) {
        int gr = row0 + ty*4 + i;
        if (gr >= M) continue;
        #pragma unroll
        for (int j = 0; j < 4; j++) {
            int gc = col0 + tx*4 + j;
            if (gc >= N) continue;
            float v = acc[i][j] + bias[gc];
            if (act == 1) v = gelu_f(v);
            if (resid) v += resid[(size_t)gr*N + gc];
            C[(size_t)gr*N + gc] = v;
        }
    }
}

// ---------------- LayerNorm (row mapping supports t[:,1:] and cls-only) ---------
// rows = gridDim.x; src row = (r/toks_out)*n_src_tokens + r%toks_out + tok_off
__global__ void ln_kernel(const float* __restrict__ src, float* __restrict__ dst,
                          const float* __restrict__ gamma, const float* __restrict__ beta,
                          int n_src_tokens, int toks_out, int tok_off)
{
    int r = blockIdx.x;
    int b = r / toks_out;
    int n = r % toks_out + tok_off;
    const float* x = src + ((size_t)b*n_src_tokens + n)*DD;
    float* y = dst + (size_t)r*DD;
    int tid = threadIdx.x;                 // 256
    float v[3];
    float s = 0.f, s2 = 0.f;
    #pragma unroll
    for (int i = 0; i < 3; i++) { v[i] = x[tid + i*256]; s += v[i]; s2 += v[i]*v[i]; }
    __shared__ float sh1[8], sh2[8];
    #pragma unroll
    for (int o = 16; o > 0; o >>= 1) {
        s  += __shfl_xor_sync(0xffffffffu, s,  o);
        s2 += __shfl_xor_sync(0xffffffffu, s2, o);
    }
    if ((tid & 31) == 0) { sh1[tid>>5] = s; sh2[tid>>5] = s2; }
    __syncthreads();
    float ts = 0.f, ts2 = 0.f;
    #pragma unroll
    for (int w = 0; w < 8; w++) { ts += sh1[w]; ts2 += sh2[w]; }
    float mean = ts * (1.f/768.f);
    float var  = ts2 * (1.f/768.f) - mean*mean;
    float rstd = rsqrtf(var + 1e-6f);
    #pragma unroll
    for (int i = 0; i < 3; i++) {
        int c = tid + i*256;
        y[c] = (v[i] - mean) * rstd * gamma[c] + beta[c];
    }
}

// ---------------- fused attention: one block per (b,h,query-row) ----------------
__global__ void attn_kernel(const float* __restrict__ qkv, float* __restrict__ o, int N)
{
    int i = blockIdx.x % N;
    int h = (blockIdx.x / N) % NHD;
    int b = blockIdx.x / (N*NHD);
    int tid = threadIdx.x;                 // 128
    int lane = tid & 31, wid = tid >> 5;
    __shared__ float q[HD];
    __shared__ float p[NMAX];
    __shared__ float red[4], red2[4];
    const size_t base = (size_t)b*N*2304;
    if (tid < HD) q[tid] = qkv[base + (size_t)i*2304 + h*HD + tid];
    __syncthreads();
    for (int j = tid; j < N; j += 128) {
        const float* krow = qkv + base + (size_t)j*2304 + 768 + h*HD;
        float s = 0.f;
        #pragma unroll
        for (int d = 0; d < HD; d++) s = fmaf(q[d], krow[d], s);
        p[j] = s * ATTN_SCALE;
    }
    __syncthreads();
    float m = -1e30f;
    for (int j = tid; j < N; j += 128) m = fmaxf(m, p[j]);
    #pragma unroll
    for (int o2 = 16; o2 > 0; o2 >>= 1) m = fmaxf(m, __shfl_xor_sync(0xffffffffu, m, o2));
    if (lane == 0) red[wid] = m;
    __syncthreads();
    m = fmaxf(fmaxf(red[0], red[1]), fmaxf(red[2], red[3]));
    float ls = 0.f;
    for (int j = tid; j < N; j += 128) { float e = expf(p[j] - m); p[j] = e; ls += e; }
    #pragma unroll
    for (int o2 = 16; o2 > 0; o2 >>= 1) ls += __shfl_xor_sync(0xffffffffu, ls, o2);
    if (lane == 0) red2[wid] = ls;
    __syncthreads();
    float inv = 1.f / (red2[0] + red2[1] + red2[2] + red2[3]);
    if (tid < HD) {
        const float* vbase = qkv + base + 1536 + h*HD + tid;
        float a0 = 0.f, a1 = 0.f, a2 = 0.f, a3 = 0.f;
        int j = 0;
        for (; j + 3 < N; j += 4) {
            const float* vp = vbase + (size_t)j*2304;
            a0 = fmaf(p[j],   vp[0],    a0);
            a1 = fmaf(p[j+1], vp[2304], a1);
            a2 = fmaf(p[j+2], vp[4608], a2);
            a3 = fmaf(p[j+3], vp[6912], a3);
        }
        for (; j < N; j++) a0 = fmaf(p[j], vbase[(size_t)j*2304], a0);
        o[((size_t)b*N + i)*DD + h*HD + tid] = (a0 + a1 + a2 + a3) * inv;
    }
}

// ---------------- predictor helpers ----------------
__global__ void globmean_kernel(const float* __restrict__ hidden, float* __restrict__ glob, int L)
{
    int b = blockIdx.x;
    int c = threadIdx.x;                   // 384
    float s = 0.f;
    for (int l = 0; l < L; l++) s += hidden[((size_t)b*L + l)*DD + 384 + c];
    glob[b*384 + c] = s / (float)L;
}

__global__ void combine_kernel(const float* __restrict__ hidden, const float* __restrict__ glob,
                               float* __restrict__ h2, int L)
{
    int i = blockIdx.x * blockDim.x + threadIdx.x;
    int total = BB*L*DD;
    if (i >= total) return;
    int c = i % DD;
    int r = i / DD;
    int b = r / L;
    h2[i] = (c < 384) ? hidden[i] : glob[b*384 + (c - 384)];
}

// exact jax top_k order via rank counting (score desc, index asc tie-break).
// log_sigmoid is monotonic -> ranking on the pre-activation is identical.
__global__ void topk_kernel(const float* __restrict__ score, int* __restrict__ idx, int L, int k)
{
    int b = blockIdx.x;
    __shared__ float s[LMAX];
    int t = threadIdx.x;                   // 256
    for (int j = t; j < L; j += blockDim.x) s[j] = score[b*L + j];
    __syncthreads();
    if (t < L) {
        float my = s[t];
        int rank = 0;
        for (int j = 0; j < L; j++) {
            float v = s[j];
            rank += (v > my) || (v == my && j < t);
        }
        if (rank < k) idx[b*LMAX + rank] = t;
    }
}

__global__ void gather_kernel(const float* __restrict__ tin, const int* __restrict__ idx,
                              float* __restrict__ tout, int Nin, int Nout)
{
    int i = blockIdx.x * blockDim.x + threadIdx.x;
    int total = BB*Nout*DD;
    if (i >= total) return;
    int c = i % DD;
    int r = i / DD;
    int b = r / Nout;
    int j = r % Nout;
    int n = (j == 0) ? 0 : (1 + idx[b*LMAX + (j - 1)]);
    tout[i] = tin[((size_t)b*Nin + n)*DD + c];
}

// ---------------- host orchestration ----------------
static inline void launch_gemm(const float* A, const float* W, const float* bias,
                               const float* resid, float* C, int M, int N, int K, int act)
{
    dim3 grid((N + 63) / 64, (M + 63) / 64);
    dim3 block(16, 16);
    gemm_kernel<<<grid, block>>>(A, W, bias, resid, C, M, N, K, act);
}

extern "C" void kernel_launch(void* const* d_in, const int* in_sizes, int n_in,
                              void* d_out, int out_size)
{
    const float* x       = (const float*)d_in[0];
    const float* patch_w = (const float*)d_in[1];
    const float* patch_b = (const float*)d_in[2];
    const float* cls_tok = (const float*)d_in[3];
    const float* pos     = (const float*)d_in[4];
    const float* ln1_g   = (const float*)d_in[5];
    const float* ln1_b   = (const float*)d_in[6];
    const float* qkv_w   = (const float*)d_in[7];
    const float* qkv_b   = (const float*)d_in[8];
    const float* proj_w  = (const float*)d_in[9];
    const float* proj_b  = (const float*)d_in[10];
    const float* ln2_g   = (const float*)d_in[11];
    const float* ln2_b   = (const float*)d_in[12];
    const float* fc1_w   = (const float*)d_in[13];
    const float* fc1_b   = (const float*)d_in[14];
    const float* fc2_w   = (const float*)d_in[15];
    const float* fc2_b   = (const float*)d_in[16];
    const float* pln_g   = (const float*)d_in[17];
    const float* pln_b   = (const float*)d_in[18];
    const float* pin_w   = (const float*)d_in[19];
    const float* pin_b   = (const float*)d_in[20];
    const float* pw1     = (const float*)d_in[21];
    const float* pb1     = (const float*)d_in[22];
    const float* pw2     = (const float*)d_in[23];
    const float* pb2     = (const float*)d_in[24];
    const float* pw3     = (const float*)d_in[25];
    const float* pb3     = (const float*)d_in[26];
    const float* norm_g  = (const float*)d_in[27];
    const float* norm_b  = (const float*)d_in[28];
    const float* head_w  = (const float*)d_in[29];
    const float* head_b  = (const float*)d_in[30];
    (void)in_sizes; (void)n_in; (void)out_size;

    void* p;
    cudaGetSymbolAddress(&p, g_t0);    float* t0    = (float*)p;
    cudaGetSymbolAddress(&p, g_t1);    float* t1    = (float*)p;
    cudaGetSymbolAddress(&p, g_ln);    float* lnb   = (float*)p;
    cudaGetSymbolAddress(&p, g_qkv);   float* qkvb  = (float*)p;
    cudaGetSymbolAddress(&p, g_ao);    float* ao    = (float*)p;
    cudaGetSymbolAddress(&p, g_mlp);   float* mlpb  = (float*)p;
    cudaGetSymbolAddress(&p, g_pa);    float* pa    = (float*)p;
    cudaGetSymbolAddress(&p, g_pb);    float* pbuf  = (float*)p;
    cudaGetSymbolAddress(&p, g_glob);  float* glob  = (float*)p;
    cudaGetSymbolAddress(&p, g_score); float* score = (float*)p;
    cudaGetSymbolAddress(&p, g_idx);   int*   gidx  = (int*)p;
    cudaGetSymbolAddress(&p, g_cls);   float* clsb  = (float*)p;

    // patch embedding
    { int total = BB*LMAX*DD; im2col_kernel<<<(total + 255)/256, 256>>>(x, pa); }
    launch_gemm(pa, patch_w, patch_b, nullptr, pbuf, BB*LMAX, DD, DD, 0);
    { int total = BB*NMAX*DD; assemble_kernel<<<(total + 255)/256, 256>>>(pbuf, cls_tok, pos, t0); }

    float* ta = t0;
    float* tb = t1;
    int N = NMAX;
    const int kkeep[3] = {138, 97, 68};

    for (int i = 0; i < 12; i++) {
        int s = (i == 3) ? 0 : (i == 6) ? 1 : (i == 9) ? 2 : -1;
        if (s >= 0) {
            int L = N - 1;
            int M = BB * L;
            ln_kernel<<<M, 256>>>(ta, pa, pln_g + s*DD, pln_b + s*DD, N, L, 1);
            launch_gemm(pa, pin_w + (size_t)s*DD*DD, pin_b + s*DD, nullptr, pbuf, M, DD, DD, 1);
            globmean_kernel<<<BB, 384>>>(pbuf, glob, L);
            { int total = M*DD; combine_kernel<<<(total + 255)/256, 256>>>(pbuf, glob, pa, L); }
            launch_gemm(pa,   pw1 + (size_t)s*384*DD,  pb1 + s*384, nullptr, pbuf,  M, 384, DD,  1);
            launch_gemm(pbuf, pw2 + (size_t)s*192*384, pb2 + s*192, nullptr, pa,    M, 192, 384, 1);
            launch_gemm(pa,   pw3 + (size_t)s*192,     pb3 + s,     nullptr, score, M, 1,   192, 0);
            topk_kernel<<<BB, 256>>>(score, gidx, L, kkeep[s]);
            int Nn = kkeep[s] + 1;
            { int total = BB*Nn*DD; gather_kernel<<<(total + 255)/256, 256>>>(ta, gidx, tb, N, Nn); }
            float* tmp = ta; ta = tb; tb = tmp;
            N = Nn;
        }
        int M = BB * N;
        ln_kernel<<<M, 256>>>(ta, lnb, ln1_g + i*DD, ln1_b + i*DD, N, N, 0);
        launch_gemm(lnb, qkv_w + (size_t)i*2304*DD, qkv_b + i*2304, nullptr, qkvb, M, 2304, DD, 0);
        attn_kernel<<<BB*NHD*N, 128>>>(qkvb, ao, N);
        launch_gemm(ao, proj_w + (size_t)i*DD*DD, proj_b + i*DD, ta, tb, M, DD, DD, 0);
        ln_kernel<<<M, 256>>>(tb, lnb, ln2_g + i*DD, ln2_b + i*DD, N, N, 0);
        launch_gemm(lnb, fc1_w + (size_t)i*3072*DD, fc1_b + i*3072, nullptr, mlpb, M, 3072, DD, 1);
        launch_gemm(mlpb, fc2_w + (size_t)i*DD*3072, fc2_b + i*DD, tb, ta, M, DD, 3072, 0);
    }

    // final LN on cls token + classification head
    ln_kernel<<<BB, 256>>>(ta, clsb, norm_g, norm_b, N, 1, 0);
    launch_gemm(clsb, head_w, head_b, nullptr, (float*)d_out, BB, 1000, DD, 0);
}

// round 4
// speedup vs baseline: 1.3239x; 1.3239x over previous
#include <cuda_runtime.h>
#include <math.h>
#include <stdint.h>

#define BB   32
#define DD   768
#define NHD  12
#define HD   64
#define NMAX 197
#define LMAX 196
#define ATTN_SCALE 0.125f

// ---------------- scratch (device globals; no allocation allowed) ----------------
__device__ float g_t0[BB*NMAX*DD];
__device__ float g_t1[BB*NMAX*DD];
__device__ float g_ln[BB*NMAX*DD];
__device__ float g_qkv[BB*NMAX*2304];
__device__ float g_ao[BB*NMAX*DD];
__device__ float g_mlp[BB*NMAX*3072];
__device__ float g_pa[BB*LMAX*DD];
__device__ float g_pb[BB*LMAX*DD];
__device__ float g_glob[BB*384];
__device__ float g_score[BB*LMAX];
__device__ int   g_idx[BB*LMAX];
__device__ float g_cls[BB*DD];

__device__ __forceinline__ float gelu_f(float x) {
    return 0.5f * x * (1.f + erff(x * 0.70710678118654752440f));
}

// ---------------- im2col for patch embedding ----------------
__global__ void im2col_kernel(const float* __restrict__ x, float* __restrict__ p) {
    int i = blockIdx.x * blockDim.x + threadIdx.x;
    const int total = BB*LMAX*DD;
    if (i >= total) return;
    int c = i % DD;
    int r = i / DD;
    int b = r / LMAX;
    int l = r % LMAX;
    int gy = l / 14, gx = l % 14;
    int ch = c / 256, rem = c % 256, py = rem / 16, px = rem % 16;
    p[i] = x[(((size_t)b*3 + ch)*224 + gy*16 + py)*224 + gx*16 + px];
}

// assemble t = [cls | patches] + pos
__global__ void assemble_kernel(const float* __restrict__ pe, const float* __restrict__ cls,
                                const float* __restrict__ pos, float* __restrict__ t) {
    int i = blockIdx.x * blockDim.x + threadIdx.x;
    const int total = BB*NMAX*DD;
    if (i >= total) return;
    int d = i % DD;
    int n = (i / DD) % NMAX;
    int b = i / (DD*NMAX);
    float v = (n == 0) ? cls[d] : pe[((size_t)b*LMAX + (n-1))*DD + d];
    t[i] = v + pos[n*DD + d];
}

// =====================================================================
// Tensor-core GEMM: C = act(A[M,K] @ W[N,K]^T + bias) (+resid)
// 3xTF32 (hi/lo split) for ~fp32 accuracy, fp32 accumulate.
// 128x128x16 CTA tile, 256 threads, warp grid 2x4, warp tile 64x32.
// =====================================================================
#define SK 20   // smem row stride (floats): all 32 banks hit once per frag load

__device__ __forceinline__ uint32_t f2tf(float f) {
    uint32_t u;
    asm("cvt.rna.tf32.f32 %0, %1;" : "=r"(u) : "f"(f));
    return u;
}

__device__ __forceinline__ void mma_tf32(float d[4], const uint32_t a[4], const uint32_t b[2]) {
    asm volatile(
        "mma.sync.aligned.m16n8k8.row.col.f32.tf32.tf32.f32 "
        "{%0,%1,%2,%3}, {%4,%5,%6,%7}, {%8,%9}, {%0,%1,%2,%3};\n"
        : "+f"(d[0]), "+f"(d[1]), "+f"(d[2]), "+f"(d[3])
        : "r"(a[0]), "r"(a[1]), "r"(a[2]), "r"(a[3]), "r"(b[0]), "r"(b[1]));
}

__global__ __launch_bounds__(256)
void gemm_tc_kernel(const float* __restrict__ A, const float* __restrict__ W,
                    const float* __restrict__ bias, const float* __restrict__ resid,
                    float* __restrict__ C, int M, int N, int K, int act)
{
    __shared__ __align__(16) float Ah[128][SK];
    __shared__ __align__(16) float Al[128][SK];
    __shared__ __align__(16) float Bh[128][SK];
    __shared__ __align__(16) float Bl[128][SK];

    int tid = threadIdx.x;
    int lane = tid & 31, w = tid >> 5;
    int wm = w >> 2, wn = w & 3;          // warp grid 2x4
    int g = lane >> 2, tig = lane & 3;    // mma quad coords
    int row0 = blockIdx.y * 128, col0 = blockIdx.x * 128;

    float acc[4][4][4];
    #pragma unroll
    for (int i = 0; i < 4; i++)
        #pragma unroll
        for (int j = 0; j < 4; j++)
            #pragma unroll
            for (int q = 0; q < 4; q++) acc[i][j][q] = 0.f;

    int ldr = tid >> 2;          // 0..63
    int ldc = (tid & 3) * 4;     // 0,4,8,12

    const float4 z4 = make_float4(0.f, 0.f, 0.f, 0.f);
    float4 pa[2], pb[2];

    // initial prefetch (k0 = 0)
    #pragma unroll
    for (int i = 0; i < 2; i++) {
        int gr = row0 + ldr + i*64;
        pa[i] = (gr < M) ? *(const float4*)(A + (size_t)gr*K + ldc) : z4;
        int wr = col0 + ldr + i*64;
        pb[i] = (wr < N) ? *(const float4*)(W + (size_t)wr*K + ldc) : z4;
    }

    int ktiles = K >> 4;
    for (int kt = 0; kt < ktiles; kt++) {
        // split into tf32 hi/lo and store to smem
        #pragma unroll
        for (int i = 0; i < 2; i++) {
            int r = ldr + i*64;
            float va[4] = {pa[i].x, pa[i].y, pa[i].z, pa[i].w};
            float vb[4] = {pb[i].x, pb[i].y, pb[i].z, pb[i].w};
            float4 ah4, al4, bh4, bl4;
            float* ahp = &ah4.x; float* alp = &al4.x;
            float* bhp = &bh4.x; float* blp = &bl4.x;
            #pragma unroll
            for (int j = 0; j < 4; j++) {
                uint32_t h = f2tf(va[j]);
                ahp[j] = __uint_as_float(h);
                alp[j] = va[j] - ahp[j];
                uint32_t hb = f2tf(vb[j]);
                bhp[j] = __uint_as_float(hb);
                blp[j] = vb[j] - bhp[j];
            }
            *(float4*)&Ah[r][ldc] = ah4;
            *(float4*)&Al[r][ldc] = al4;
            *(float4*)&Bh[r][ldc] = bh4;
            *(float4*)&Bl[r][ldc] = bl4;
        }
        __syncthreads();

        // prefetch next tile (overlaps with mma below)
        if (kt + 1 < ktiles) {
            int k0 = (kt + 1) << 4;
            #pragma unroll
            for (int i = 0; i < 2; i++) {
                int gr = row0 + ldr + i*64;
                pa[i] = (gr < M) ? *(const float4*)(A + (size_t)gr*K + k0 + ldc) : z4;
                int wr = col0 + ldr + i*64;
                pb[i] = (wr < N) ? *(const float4*)(W + (size_t)wr*K + k0 + ldc) : z4;
            }
        }

        // compute: 2 k-steps of 8
        #pragma unroll
        for (int ks = 0; ks < 2; ks++) {
            int k = ks*8 + tig;
            uint32_t bhf[4][2], blf[4][2];
            #pragma unroll
            for (int nt = 0; nt < 4; nt++) {
                int n = wn*32 + nt*8 + g;
                bhf[nt][0] = __float_as_uint(Bh[n][k]);
                bhf[nt][1] = __float_as_uint(Bh[n][k+4]);
                blf[nt][0] = __float_as_uint(Bl[n][k]);
                blf[nt][1] = __float_as_uint(Bl[n][k+4]);
            }
            #pragma unroll
            for (int mt = 0; mt < 4; mt++) {
                int r = wm*64 + mt*16 + g;
                uint32_t ah[4], al[4];
                ah[0] = __float_as_uint(Ah[r][k]);
                ah[1] = __float_as_uint(Ah[r+8][k]);
                ah[2] = __float_as_uint(Ah[r][k+4]);
                ah[3] = __float_as_uint(Ah[r+8][k+4]);
                al[0] = __float_as_uint(Al[r][k]);
                al[1] = __float_as_uint(Al[r+8][k]);
                al[2] = __float_as_uint(Al[r][k+4]);
                al[3] = __float_as_uint(Al[r+8][k+4]);
                #pragma unroll
                for (int nt = 0; nt < 4; nt++) {
                    mma_tf32(acc[mt][nt], al, bhf[nt]);   // lo*hi
                    mma_tf32(acc[mt][nt], ah, blf[nt]);   // hi*lo
                    mma_tf32(acc[mt][nt], ah, bhf[nt]);   // hi*hi
                }
            }
        }
        __syncthreads();
    }

    // epilogue
    #pragma unroll
    for (int mt = 0; mt < 4; mt++) {
        #pragma unroll
        for (int nt = 0; nt < 4; nt++) {
            int gc0 = col0 + wn*32 + nt*8 + 2*tig;
            #pragma unroll
            for (int half = 0; half < 2; half++) {
                int gr = row0 + wm*64 + mt*16 + g + half*8;
                if (gr >= M) continue;
                #pragma unroll
                for (int j = 0; j < 2; j++) {
                    int gc = gc0 + j;
                    if (gc >= N) continue;
                    float v = acc[mt][nt][half*2 + j] + bias[gc];
                    if (act == 1) v = gelu_f(v);
                    if (resid) v += resid[(size_t)gr*N + gc];
                    C[(size_t)gr*N + gc] = v;
                }
            }
        }
    }
}

// ---------------- SIMT GEMM (kept for tiny shapes: N=1 predictor head, class head) -
__global__ void gemm_kernel(const float* __restrict__ A, const float* __restrict__ W,
                            const float* __restrict__ bias, const float* __restrict__ resid,
                            float* __restrict__ C, int M, int N, int K, int act)
{
    __shared__ float As[16][65];
    __shared__ float Ws[16][65];
    int tx = threadIdx.x, ty = threadIdx.y;
    int tid = ty*16 + tx;
    int row0 = blockIdx.y*64, col0 = blockIdx.x*64;
    float acc[4][4] = {};
    for (int k0 = 0; k0 < K; k0 += 16) {
        #pragma unroll
        for (int i = 0; i < 4; i++) {
            int idx = tid + i*256;
            int r = idx >> 4;
            int c = idx & 15;
            int gr = row0 + r;
            As[c][r] = (gr < M) ? A[(size_t)gr*K + k0 + c] : 0.f;
            int wr = col0 + r;
            Ws[c][r] = (wr < N) ? W[(size_t)wr*K + k0 + c] : 0.f;
        }
        __syncthreads();
        #pragma unroll
        for (int kk = 0; kk < 16; kk++) {
            float a[4], bb[4];
            #pragma unroll
            for (int i = 0; i < 4; i++) a[i] = As[kk][ty*4+i];
            #pragma unroll
            for (int j = 0; j < 4; j++) bb[j] = Ws[kk][tx*4+j];
            #pragma unroll
            for (int i = 0; i < 4; i++)
                #pragma unroll
                for (int j = 0; j < 4; j++)
                    acc[i][j] = fmaf(a[i], bb[j], acc[i][j]);
        }
        __syncthreads();
    }
    #pragma unroll
    for (int i = 0; i < 4; i++) {
        int gr = row0 + ty*4 + i;
        if (gr >= M) continue;
        #pragma unroll
        for (int j = 0; j < 4; j++) {
            int gc = col0 + tx*4 + j;
            if (gc >= N) continue;
            float v = acc[i][j] + bias[gc];
            if (act == 1) v = gelu_f(v);
            if (resid) v += resid[(size_t)gr*N + gc];
            C[(size_t)gr*N + gc] = v;
        }
    }
}

// ---------------- LayerNorm (row mapping supports t[:,1:] and cls-only) ---------
__global__ void ln_kernel(const float* __restrict__ src, float* __restrict__ dst,
                          const float* __restrict__ gamma, const float* __restrict__ beta,
                          int n_src_tokens, int toks_out, int tok_off)
{
    int r = blockIdx.x;
    int b = r / toks_out;
    int n = r % toks_out + tok_off;
    const float* x = src + ((size_t)b*n_src_tokens + n)*DD;
    float* y = dst + (size_t)r*DD;
    int tid = threadIdx.x;                 // 256
    float v[3];
    float s = 0.f, s2 = 0.f;
    #pragma unroll
    for (int i = 0; i < 3; i++) { v[i] = x[tid + i*256]; s += v[i]; s2 += v[i]*v[i]; }
    __shared__ float sh1[8], sh2[8];
    #pragma unroll
    for (int o = 16; o > 0; o >>= 1) {
        s  += __shfl_xor_sync(0xffffffffu, s,  o);
        s2 += __shfl_xor_sync(0xffffffffu, s2, o);
    }
    if ((tid & 31) == 0) { sh1[tid>>5] = s; sh2[tid>>5] = s2; }
    __syncthreads();
    float ts = 0.f, ts2 = 0.f;
    #pragma unroll
    for (int w = 0; w < 8; w++) { ts += sh1[w]; ts2 += sh2[w]; }
    float mean = ts * (1.f/768.f);
    float var  = ts2 * (1.f/768.f) - mean*mean;
    float rstd = rsqrtf(var + 1e-6f);
    #pragma unroll
    for (int i = 0; i < 3; i++) {
        int c = tid + i*256;
        y[c] = (v[i] - mean) * rstd * gamma[c] + beta[c];
    }
}

// ---------------- fused attention: one block per (b,h,query-row) ----------------
__global__ void attn_kernel(const float* __restrict__ qkv, float* __restrict__ o, int N)
{
    int i = blockIdx.x % N;
    int h = (blockIdx.x / N) % NHD;
    int b = blockIdx.x / (N*NHD);
    int tid = threadIdx.x;                 // 128
    int lane = tid & 31, wid = tid >> 5;
    __shared__ float q[HD];
    __shared__ float p[NMAX];
    __shared__ float red[4], red2[4];
    const size_t base = (size_t)b*N*2304;
    if (tid < HD) q[tid] = qkv[base + (size_t)i*2304 + h*HD + tid];
    __syncthreads();
    for (int j = tid; j < N; j += 128) {
        const float* krow = qkv + base + (size_t)j*2304 + 768 + h*HD;
        float s = 0.f;
        #pragma unroll
        for (int d = 0; d < HD; d++) s = fmaf(q[d], krow[d], s);
        p[j] = s * ATTN_SCALE;
    }
    __syncthreads();
    float m = -1e30f;
    for (int j = tid; j < N; j += 128) m = fmaxf(m, p[j]);
    #pragma unroll
    for (int o2 = 16; o2 > 0; o2 >>= 1) m = fmaxf(m, __shfl_xor_sync(0xffffffffu, m, o2));
    if (lane == 0) red[wid] = m;
    __syncthreads();
    m = fmaxf(fmaxf(red[0], red[1]), fmaxf(red[2], red[3]));
    float ls = 0.f;
    for (int j = tid; j < N; j += 128) { float e = expf(p[j] - m); p[j] = e; ls += e; }
    #pragma unroll
    for (int o2 = 16; o2 > 0; o2 >>= 1) ls += __shfl_xor_sync(0xffffffffu, ls, o2);
    if (lane == 0) red2[wid] = ls;
    __syncthreads();
    float inv = 1.f / (red2[0] + red2[1] + red2[2] + red2[3]);
    if (tid < HD) {
        const float* vbase = qkv + base + 1536 + h*HD + tid;
        float a0 = 0.f, a1 = 0.f, a2 = 0.f, a3 = 0.f;
        int j = 0;
        for (; j + 3 < N; j += 4) {
            const float* vp = vbase + (size_t)j*2304;
            a0 = fmaf(p[j],   vp[0],    a0);
            a1 = fmaf(p[j+1], vp[2304], a1);
            a2 = fmaf(p[j+2], vp[4608], a2);
            a3 = fmaf(p[j+3], vp[6912], a3);
        }
        for (; j < N; j++) a0 = fmaf(p[j], vbase[(size_t)j*2304], a0);
        o[((size_t)b*N + i)*DD + h*HD + tid] = (a0 + a1 + a2 + a3) * inv;
    }
}

// ---------------- predictor helpers ----------------
__global__ void globmean_kernel(const float* __restrict__ hidden, float* __restrict__ glob, int L)
{
    int b = blockIdx.x;
    int c = threadIdx.x;                   // 384
    float s = 0.f;
    for (int l = 0; l < L; l++) s += hidden[((size_t)b*L + l)*DD + 384 + c];
    glob[b*384 + c] = s / (float)L;
}

__global__ void combine_kernel(const float* __restrict__ hidden, const float* __restrict__ glob,
                               float* __restrict__ h2, int L)
{
    int i = blockIdx.x * blockDim.x + threadIdx.x;
    int total = BB*L*DD;
    if (i >= total) return;
    int c = i % DD;
    int r = i / DD;
    int b = r / L;
    h2[i] = (c < 384) ? hidden[i] : glob[b*384 + (c - 384)];
}

// exact jax top_k order via rank counting (score desc, index asc tie-break).
__global__ void topk_kernel(const float* __restrict__ score, int* __restrict__ idx, int L, int k)
{
    int b = blockIdx.x;
    __shared__ float s[LMAX];
    int t = threadIdx.x;                   // 256
    for (int j = t; j < L; j += blockDim.x) s[j] = score[b*L + j];
    __syncthreads();
    if (t < L) {
        float my = s[t];
        int rank = 0;
        for (int j = 0; j < L; j++) {
            float v = s[j];
            rank += (v > my) || (v == my && j < t);
        }
        if (rank < k) idx[b*LMAX + rank] = t;
    }
}

__global__ void gather_kernel(const float* __restrict__ tin, const int* __restrict__ idx,
                              float* __restrict__ tout, int Nin, int Nout)
{
    int i = blockIdx.x * blockDim.x + threadIdx.x;
    int total = BB*Nout*DD;
    if (i >= total) return;
    int c = i % DD;
    int r = i / DD;
    int b = r / Nout;
    int j = r % Nout;
    int n = (j == 0) ? 0 : (1 + idx[b*LMAX + (j - 1)]);
    tout[i] = tin[((size_t)b*Nin + n)*DD + c];
}

// ---------------- host orchestration ----------------
static inline void launch_gemm_tc(const float* A, const float* W, const float* bias,
                                  const float* resid, float* C, int M, int N, int K, int act)
{
    dim3 grid((N + 127) / 128, (M + 127) / 128);
    gemm_tc_kernel<<<grid, 256>>>(A, W, bias, resid, C, M, N, K, act);
}

static inline void launch_gemm(const float* A, const float* W, const float* bias,
                               const float* resid, float* C, int M, int N, int K, int act)
{
    dim3 grid((N + 63) / 64, (M + 63) / 64);
    dim3 block(16, 16);
    gemm_kernel<<<grid, block>>>(A, W, bias, resid, C, M, N, K, act);
}

extern "C" void kernel_launch(void* const* d_in, const int* in_sizes, int n_in,
                              void* d_out, int out_size)
{
    const float* x       = (const float*)d_in[0];
    const float* patch_w = (const float*)d_in[1];
    const float* patch_b = (const float*)d_in[2];
    const float* cls_tok = (const float*)d_in[3];
    const float* pos     = (const float*)d_in[4];
    const float* ln1_g   = (const float*)d_in[5];
    const float* ln1_b   = (const float*)d_in[6];
    const float* qkv_w   = (const float*)d_in[7];
    const float* qkv_b   = (const float*)d_in[8];
    const float* proj_w  = (const float*)d_in[9];
    const float* proj_b  = (const float*)d_in[10];
    const float* ln2_g   = (const float*)d_in[11];
    const float* ln2_b   = (const float*)d_in[12];
    const float* fc1_w   = (const float*)d_in[13];
    const float* fc1_b   = (const float*)d_in[14];
    const float* fc2_w   = (const float*)d_in[15];
    const float* fc2_b   = (const float*)d_in[16];
    const float* pln_g   = (const float*)d_in[17];
    const float* pln_b   = (const float*)d_in[18];
    const float* pin_w   = (const float*)d_in[19];
    const float* pin_b   = (const float*)d_in[20];
    const float* pw1     = (const float*)d_in[21];
    const float* pb1     = (const float*)d_in[22];
    const float* pw2     = (const float*)d_in[23];
    const float* pb2     = (const float*)d_in[24];
    const float* pw3     = (const float*)d_in[25];
    const float* pb3     = (const float*)d_in[26];
    const float* norm_g  = (const float*)d_in[27];
    const float* norm_b  = (const float*)d_in[28];
    const float* head_w  = (const float*)d_in[29];
    const float* head_b  = (const float*)d_in[30];
    (void)in_sizes; (void)n_in; (void)out_size;

    void* p;
    cudaGetSymbolAddress(&p, g_t0);    float* t0    = (float*)p;
    cudaGetSymbolAddress(&p, g_t1);    float* t1    = (float*)p;
    cudaGetSymbolAddress(&p, g_ln);    float* lnb   = (float*)p;
    cudaGetSymbolAddress(&p, g_qkv);   float* qkvb  = (float*)p;
    cudaGetSymbolAddress(&p, g_ao);    float* ao    = (float*)p;
    cudaGetSymbolAddress(&p, g_mlp);   float* mlpb  = (float*)p;
    cudaGetSymbolAddress(&p, g_pa);    float* pa    = (float*)p;
    cudaGetSymbolAddress(&p, g_pb);    float* pbuf  = (float*)p;
    cudaGetSymbolAddress(&p, g_glob);  float* glob  = (float*)p;
    cudaGetSymbolAddress(&p, g_score); float* score = (float*)p;
    cudaGetSymbolAddress(&p, g_idx);   int*   gidx  = (int*)p;
    cudaGetSymbolAddress(&p, g_cls);   float* clsb  = (float*)p;

    // patch embedding
    { int total = BB*LMAX*DD; im2col_kernel<<<(total + 255)/256, 256>>>(x, pa); }
    launch_gemm_tc(pa, patch_w, patch_b, nullptr, pbuf, BB*LMAX, DD, DD, 0);
    { int total = BB*NMAX*DD; assemble_kernel<<<(total + 255)/256, 256>>>(pbuf, cls_tok, pos, t0); }

    float* ta = t0;
    float* tb = t1;
    int N = NMAX;
    const int kkeep[3] = {138, 97, 68};

    for (int i = 0; i < 12; i++) {
        int s = (i == 3) ? 0 : (i == 6) ? 1 : (i == 9) ? 2 : -1;
        if (s >= 0) {
            int L = N - 1;
            int M = BB * L;
            ln_kernel<<<M, 256>>>(ta, pa, pln_g + s*DD, pln_b + s*DD, N, L, 1);
            launch_gemm_tc(pa, pin_w + (size_t)s*DD*DD, pin_b + s*DD, nullptr, pbuf, M, DD, DD, 1);
            globmean_kernel<<<BB, 384>>>(pbuf, glob, L);
            { int total = M*DD; combine_kernel<<<(total + 255)/256, 256>>>(pbuf, glob, pa, L); }
            launch_gemm_tc(pa,   pw1 + (size_t)s*384*DD,  pb1 + s*384, nullptr, pbuf,  M, 384, DD,  1);
            launch_gemm_tc(pbuf, pw2 + (size_t)s*192*384, pb2 + s*192, nullptr, pa,    M, 192, 384, 1);
            launch_gemm(pa,   pw3 + (size_t)s*192,     pb3 + s,     nullptr, score, M, 1,   192, 0);
            topk_kernel<<<BB, 256>>>(score, gidx, L, kkeep[s]);
            int Nn = kkeep[s] + 1;
            { int total = BB*Nn*DD; gather_kernel<<<(total + 255)/256, 256>>>(ta, gidx, tb, N, Nn); }
            float* tmp = ta; ta = tb; tb = tmp;
            N = Nn;
        }
        int M = BB * N;
        ln_kernel<<<M, 256>>>(ta, lnb, ln1_g + i*DD, ln1_b + i*DD, N, N, 0);
        launch_gemm_tc(lnb, qkv_w + (size_t)i*2304*DD, qkv_b + i*2304, nullptr, qkvb, M, 2304, DD, 0);
        attn_kernel<<<BB*NHD*N, 128>>>(qkvb, ao, N);
        launch_gemm_tc(ao, proj_w + (size_t)i*DD*DD, proj_b + i*DD, ta, tb, M, DD, DD, 0);
        ln_kernel<<<M, 256>>>(tb, lnb, ln2_g + i*DD, ln2_b + i*DD, N, N, 0);
        launch_gemm_tc(lnb, fc1_w + (size_t)i*3072*DD, fc1_b + i*3072, nullptr, mlpb, M, 3072, DD, 1);
        launch_gemm_tc(mlpb, fc2_w + (size_t)i*DD*3072, fc2_b + i*DD, tb, ta, M, DD, 3072, 0);
    }

    // final LN on cls token + classification head
    ln_kernel<<<BB, 256>>>(ta, clsb, norm_g, norm_b, N, 1, 0);
    launch_gemm(clsb, head_w, head_b, nullptr, (float*)d_out, BB, 1000, DD, 0);
}

// round 5
// speedup vs baseline: 2.7386x; 2.0686x over previous
#include <cuda_runtime.h>
#include <math.h>
#include <stdint.h>

#define BB   32
#define DD   768
#define NHD  12
#define HD   64
#define NMAX 197
#define LMAX 196
#define ATTN_SCALE 0.125f

// ---------------- scratch (device globals; no allocation allowed) ----------------
__device__ float g_t0[BB*NMAX*DD];
__device__ float g_t1[BB*NMAX*DD];
__device__ float g_ln[BB*NMAX*DD];
__device__ float g_qkv[BB*NMAX*2304];
__device__ float g_ao[BB*NMAX*DD];
__device__ float g_mlp[BB*NMAX*3072];
__device__ float g_pa[BB*LMAX*DD];
__device__ float g_pb[BB*LMAX*DD];
__device__ float g_glob[BB*384];
__device__ float g_score[BB*LMAX];
__device__ int   g_idx[BB*LMAX];
__device__ float g_cls[BB*DD];
__device__ float g_att[(size_t)BB*NHD*NMAX*NMAX];   // attention scores/probs (~60 MB)

__device__ __forceinline__ float gelu_f(float x) {
    return 0.5f * x * (1.f + erff(x * 0.70710678118654752440f));
}

// ---------------- im2col for patch embedding ----------------
__global__ void im2col_kernel(const float* __restrict__ x, float* __restrict__ p) {
    int i = blockIdx.x * blockDim.x + threadIdx.x;
    const int total = BB*LMAX*DD;
    if (i >= total) return;
    int c = i % DD;
    int r = i / DD;
    int b = r / LMAX;
    int l = r % LMAX;
    int gy = l / 14, gx = l % 14;
    int ch = c / 256, rem = c % 256, py = rem / 16, px = rem % 16;
    p[i] = x[(((size_t)b*3 + ch)*224 + gy*16 + py)*224 + gx*16 + px];
}

// assemble t = [cls | patches] + pos
__global__ void assemble_kernel(const float* __restrict__ pe, const float* __restrict__ cls,
                                const float* __restrict__ pos, float* __restrict__ t) {
    int i = blockIdx.x * blockDim.x + threadIdx.x;
    const int total = BB*NMAX*DD;
    if (i >= total) return;
    int d = i % DD;
    int n = (i / DD) % NMAX;
    int b = i / (DD*NMAX);
    float v = (n == 0) ? cls[d] : pe[((size_t)b*LMAX + (n-1))*DD + d];
    t[i] = v + pos[n*DD + d];
}

// =====================================================================
// 3xTF32 mma helpers
// =====================================================================
#define SK 20   // smem row stride (floats): all 32 banks hit once per frag load

__device__ __forceinline__ uint32_t f2tf(float f) {
    uint32_t u;
    asm("cvt.rna.tf32.f32 %0, %1;" : "=r"(u) : "f"(f));
    return u;
}

__device__ __forceinline__ void mma_tf32(float d[4], const uint32_t a[4], const uint32_t b[2]) {
    asm volatile(
        "mma.sync.aligned.m16n8k8.row.col.f32.tf32.tf32.f32 "
        "{%0,%1,%2,%3}, {%4,%5,%6,%7}, {%8,%9}, {%0,%1,%2,%3};\n"
        : "+f"(d[0]), "+f"(d[1]), "+f"(d[2]), "+f"(d[3])
        : "r"(a[0]), "r"(a[1]), "r"(a[2]), "r"(a[3]), "r"(b[0]), "r"(b[1]));
}

// =====================================================================
// Tensor-core GEMM: C = act(A[M,K] @ W[N,K]^T + bias) (+resid)
// 128x128x16 CTA tile, 256 threads, warp grid 2x4, warp tile 64x32.
// =====================================================================
__global__ __launch_bounds__(256)
void gemm_tc_kernel(const float* __restrict__ A, const float* __restrict__ W,
                    const float* __restrict__ bias, const float* __restrict__ resid,
                    float* __restrict__ C, int M, int N, int K, int act)
{
    __shared__ __align__(16) float Ah[128][SK];
    __shared__ __align__(16) float Al[128][SK];
    __shared__ __align__(16) float Bh[128][SK];
    __shared__ __align__(16) float Bl[128][SK];

    int tid = threadIdx.x;
    int lane = tid & 31, w = tid >> 5;
    int wm = w >> 2, wn = w & 3;          // warp grid 2x4
    int g = lane >> 2, tig = lane & 3;    // mma quad coords
    int row0 = blockIdx.y * 128, col0 = blockIdx.x * 128;

    float acc[4][4][4];
    #pragma unroll
    for (int i = 0; i < 4; i++)
        #pragma unroll
        for (int j = 0; j < 4; j++)
            #pragma unroll
            for (int q = 0; q < 4; q++) acc[i][j][q] = 0.f;

    int ldr = tid >> 2;          // 0..63
    int ldc = (tid & 3) * 4;     // 0,4,8,12

    const float4 z4 = make_float4(0.f, 0.f, 0.f, 0.f);
    float4 pa[2], pb[2];

    // initial prefetch (k0 = 0)
    #pragma unroll
    for (int i = 0; i < 2; i++) {
        int gr = row0 + ldr + i*64;
        pa[i] = (gr < M) ? *(const float4*)(A + (size_t)gr*K + ldc) : z4;
        int wr = col0 + ldr + i*64;
        pb[i] = (wr < N) ? *(const float4*)(W + (size_t)wr*K + ldc) : z4;
    }

    int ktiles = K >> 4;
    for (int kt = 0; kt < ktiles; kt++) {
        // split into tf32 hi/lo and store to smem
        #pragma unroll
        for (int i = 0; i < 2; i++) {
            int r = ldr + i*64;
            float va[4] = {pa[i].x, pa[i].y, pa[i].z, pa[i].w};
            float vb[4] = {pb[i].x, pb[i].y, pb[i].z, pb[i].w};
            float4 ah4, al4, bh4, bl4;
            float* ahp = &ah4.x; float* alp = &al4.x;
            float* bhp = &bh4.x; float* blp = &bl4.x;
            #pragma unroll
            for (int j = 0; j < 4; j++) {
                uint32_t h = f2tf(va[j]);
                ahp[j] = __uint_as_float(h);
                alp[j] = va[j] - ahp[j];
                uint32_t hb = f2tf(vb[j]);
                bhp[j] = __uint_as_float(hb);
                blp[j] = vb[j] - bhp[j];
            }
            *(float4*)&Ah[r][ldc] = ah4;
            *(float4*)&Al[r][ldc] = al4;
            *(float4*)&Bh[r][ldc] = bh4;
            *(float4*)&Bl[r][ldc] = bl4;
        }
        __syncthreads();

        // prefetch next tile (overlaps with mma below)
        if (kt + 1 < ktiles) {
            int k0 = (kt + 1) << 4;
            #pragma unroll
            for (int i = 0; i < 2; i++) {
                int gr = row0 + ldr + i*64;
                pa[i] = (gr < M) ? *(const float4*)(A + (size_t)gr*K + k0 + ldc) : z4;
                int wr = col0 + ldr + i*64;
                pb[i] = (wr < N) ? *(const float4*)(W + (size_t)wr*K + k0 + ldc) : z4;
            }
        }

        // compute: 2 k-steps of 8
        #pragma unroll
        for (int ks = 0; ks < 2; ks++) {
            int k = ks*8 + tig;
            uint32_t bhf[4][2], blf[4][2];
            #pragma unroll
            for (int nt = 0; nt < 4; nt++) {
                int n = wn*32 + nt*8 + g;
                bhf[nt][0] = __float_as_uint(Bh[n][k]);
                bhf[nt][1] = __float_as_uint(Bh[n][k+4]);
                blf[nt][0] = __float_as_uint(Bl[n][k]);
                blf[nt][1] = __float_as_uint(Bl[n][k+4]);
            }
            #pragma unroll
            for (int mt = 0; mt < 4; mt++) {
                int r = wm*64 + mt*16 + g;
                uint32_t ah[4], al[4];
                ah[0] = __float_as_uint(Ah[r][k]);
                ah[1] = __float_as_uint(Ah[r+8][k]);
                ah[2] = __float_as_uint(Ah[r][k+4]);
                ah[3] = __float_as_uint(Ah[r+8][k+4]);
                al[0] = __float_as_uint(Al[r][k]);
                al[1] = __float_as_uint(Al[r+8][k]);
                al[2] = __float_as_uint(Al[r][k+4]);
                al[3] = __float_as_uint(Al[r+8][k+4]);
                #pragma unroll
                for (int nt = 0; nt < 4; nt++) {
                    mma_tf32(acc[mt][nt], al, bhf[nt]);   // lo*hi
                    mma_tf32(acc[mt][nt], ah, blf[nt]);   // hi*lo
                    mma_tf32(acc[mt][nt], ah, bhf[nt]);   // hi*hi
                }
            }
        }
        __syncthreads();
    }

    // epilogue
    #pragma unroll
    for (int mt = 0; mt < 4; mt++) {
        #pragma unroll
        for (int nt = 0; nt < 4; nt++) {
            int gc0 = col0 + wn*32 + nt*8 + 2*tig;
            #pragma unroll
            for (int half = 0; half < 2; half++) {
                int gr = row0 + wm*64 + mt*16 + g + half*8;
                if (gr >= M) continue;
                #pragma unroll
                for (int j = 0; j < 2; j++) {
                    int gc = gc0 + j;
                    if (gc >= N) continue;
                    float v = acc[mt][nt][half*2 + j] + bias[gc];
                    if (act == 1) v = gelu_f(v);
                    if (resid) v += resid[(size_t)gr*N + gc];
                    C[(size_t)gr*N + gc] = v;
                }
            }
        }
    }
}

// =====================================================================
// Batched attention, stage 1: scores = Q @ K^T per (b,h).
// 64x64 tile over (i,j), K=64. blockIdx.z = b*NHD+h. 3xTF32.
// =====================================================================
__global__ __launch_bounds__(256)
void attn_qk_kernel(const float* __restrict__ qkv, float* __restrict__ att, int N)
{
    __shared__ __align__(16) float Ah[64][SK];
    __shared__ __align__(16) float Al[64][SK];
    __shared__ __align__(16) float Bh[64][SK];
    __shared__ __align__(16) float Bl[64][SK];

    int tid = threadIdx.x;
    int lane = tid & 31, w = tid >> 5;
    int wm = w >> 2, wn = w & 3;          // 2x4 warps -> warp tile 32x16
    int g = lane >> 2, tig = lane & 3;
    int bh = blockIdx.z;
    int b = bh / NHD, h = bh % NHD;
    const float* Q  = qkv + (size_t)b*N*2304 + h*HD;
    const float* Kp = qkv + (size_t)b*N*2304 + 768 + h*HD;
    float* C = att + (size_t)bh*N*N;
    int row0 = blockIdx.y * 64, col0 = blockIdx.x * 64;

    float acc[2][2][4];
    #pragma unroll
    for (int i = 0; i < 2; i++)
        #pragma unroll
        for (int j = 0; j < 2; j++)
            #pragma unroll
            for (int q = 0; q < 4; q++) acc[i][j][q] = 0.f;

    int ldr = tid >> 2;           // 0..63
    int ldc = (tid & 3) * 4;      // 0,4,8,12
    const float4 z4 = make_float4(0.f, 0.f, 0.f, 0.f);

    #pragma unroll
    for (int kt = 0; kt < 4; kt++) {
        int k0 = kt * 16;
        {
            int gr = row0 + ldr;
            float4 va = (gr < N) ? *(const float4*)(Q + (size_t)gr*2304 + k0 + ldc) : z4;
            int wr = col0 + ldr;
            float4 vb = (wr < N) ? *(const float4*)(Kp + (size_t)wr*2304 + k0 + ldc) : z4;
            float av[4] = {va.x, va.y, va.z, va.w};
            float bv[4] = {vb.x, vb.y, vb.z, vb.w};
            float4 ah4, al4, bh4, bl4;
            float* ahp = &ah4.x; float* alp = &al4.x;
            float* bhp = &bh4.x; float* blp = &bl4.x;
            #pragma unroll
            for (int j = 0; j < 4; j++) {
                uint32_t hh = f2tf(av[j]);
                ahp[j] = __uint_as_float(hh);
                alp[j] = av[j] - ahp[j];
                uint32_t hb = f2tf(bv[j]);
                bhp[j] = __uint_as_float(hb);
                blp[j] = bv[j] - bhp[j];
            }
            *(float4*)&Ah[ldr][ldc] = ah4;
            *(float4*)&Al[ldr][ldc] = al4;
            *(float4*)&Bh[ldr][ldc] = bh4;
            *(float4*)&Bl[ldr][ldc] = bl4;
        }
        __syncthreads();
        #pragma unroll
        for (int ks = 0; ks < 2; ks++) {
            int k = ks*8 + tig;
            uint32_t bhf[2][2], blf[2][2];
            #pragma unroll
            for (int nt = 0; nt < 2; nt++) {
                int n = wn*16 + nt*8 + g;
                bhf[nt][0] = __float_as_uint(Bh[n][k]);
                bhf[nt][1] = __float_as_uint(Bh[n][k+4]);
                blf[nt][0] = __float_as_uint(Bl[n][k]);
                blf[nt][1] = __float_as_uint(Bl[n][k+4]);
            }
            #pragma unroll
            for (int mt = 0; mt < 2; mt++) {
                int r = wm*32 + mt*16 + g;
                uint32_t ah[4], al[4];
                ah[0] = __float_as_uint(Ah[r][k]);
                ah[1] = __float_as_uint(Ah[r+8][k]);
                ah[2] = __float_as_uint(Ah[r][k+4]);
                ah[3] = __float_as_uint(Ah[r+8][k+4]);
                al[0] = __float_as_uint(Al[r][k]);
                al[1] = __float_as_uint(Al[r+8][k]);
                al[2] = __float_as_uint(Al[r][k+4]);
                al[3] = __float_as_uint(Al[r+8][k+4]);
                #pragma unroll
                for (int nt = 0; nt < 2; nt++) {
                    mma_tf32(acc[mt][nt], al, bhf[nt]);
                    mma_tf32(acc[mt][nt], ah, blf[nt]);
                    mma_tf32(acc[mt][nt], ah, bhf[nt]);
                }
            }
        }
        __syncthreads();
    }

    #pragma unroll
    for (int mt = 0; mt < 2; mt++) {
        #pragma unroll
        for (int nt = 0; nt < 2; nt++) {
            int gc0 = col0 + wn*16 + nt*8 + 2*tig;
            #pragma unroll
            for (int half = 0; half < 2; half++) {
                int gr = row0 + wm*32 + mt*16 + g + half*8;
                if (gr >= N) continue;
                #pragma unroll
                for (int j = 0; j < 2; j++) {
                    int gc = gc0 + j;
                    if (gc < N) C[(size_t)gr*N + gc] = acc[mt][nt][half*2 + j];
                }
            }
        }
    }
}

// =====================================================================
// Batched attention, stage 2: in-place row softmax of scaled scores.
// One warp per row. exp((s - max)*SCALE) == exp(s*SCALE - max*SCALE).
// =====================================================================
__global__ void attn_softmax_kernel(float* __restrict__ att, int N, int rows)
{
    int row = blockIdx.x * 4 + (threadIdx.x >> 5);
    if (row >= rows) return;
    int lane = threadIdx.x & 31;
    float* p = att + (size_t)row * N;
    float v[7];
    int cnt = 0;
    float m = -1e30f;
    for (int j = lane; j < N; j += 32) { float s = p[j]; v[cnt++] = s; m = fmaxf(m, s); }
    #pragma unroll
    for (int o = 16; o > 0; o >>= 1) m = fmaxf(m, __shfl_xor_sync(0xffffffffu, m, o));
    float sum = 0.f;
    #pragma unroll
    for (int q = 0; q < 7; q++) {
        if (q < cnt) { v[q] = expf((v[q] - m) * ATTN_SCALE); sum += v[q]; }
    }
    #pragma unroll
    for (int o = 16; o > 0; o >>= 1) sum += __shfl_xor_sync(0xffffffffu, sum, o);
    float inv = 1.f / sum;
    cnt = 0;
    for (int j = lane; j < N; j += 32) p[j] = v[cnt++] * inv;
}

// =====================================================================
// Batched attention, stage 3: O = P @ V per (b,h).
// Tile: 64 queries x 64 head-dims, K = N (j). V transposed into smem.
// =====================================================================
__global__ __launch_bounds__(256)
void attn_pv_kernel(const float* __restrict__ att, const float* __restrict__ qkv,
                    float* __restrict__ o, int N)
{
    __shared__ __align__(16) float Ph[64][SK];
    __shared__ __align__(16) float Pl[64][SK];
    __shared__ __align__(16) float Vh[64][SK];   // [d][j]
    __shared__ __align__(16) float Vl[64][SK];

    int tid = threadIdx.x;
    int lane = tid & 31, w = tid >> 5;
    int wm = w >> 2, wn = w & 3;
    int g = lane >> 2, tig = lane & 3;
    int bh = blockIdx.z;
    int b = bh / NHD, h = bh % NHD;
    const float* P = att + (size_t)bh*N*N;
    const float* V = qkv + (size_t)b*N*2304 + 1536 + h*HD;
    float* C = o + (size_t)b*N*DD + h*HD;
    int row0 = blockIdx.y * 64;

    float acc[2][2][4];
    #pragma unroll
    for (int i = 0; i < 2; i++)
        #pragma unroll
        for (int j = 0; j < 2; j++)
            #pragma unroll
            for (int q = 0; q < 4; q++) acc[i][j][q] = 0.f;

    const float4 z4 = make_float4(0.f, 0.f, 0.f, 0.f);
    int pr = tid >> 2;            // P row (query) 0..63
    int pc = (tid & 3) * 4;       // P col base within tile
    int vj = tid >> 4;            // V row (key) within tile 0..15
    int vd = (tid & 15) * 4;      // V col base 0..60

    int ktiles = (N + 15) >> 4;
    for (int kt = 0; kt < ktiles; kt++) {
        int j0 = kt * 16;
        // P tile (scalar loads: row stride N is odd)
        {
            int gi = row0 + pr;
            float pv[4], ph[4], pl[4];
            #pragma unroll
            for (int q = 0; q < 4; q++) {
                int jj = j0 + pc + q;
                pv[q] = (gi < N && jj < N) ? P[(size_t)gi*N + jj] : 0.f;
                uint32_t hh = f2tf(pv[q]);
                ph[q] = __uint_as_float(hh);
                pl[q] = pv[q] - ph[q];
            }
            *(float4*)&Ph[pr][pc] = make_float4(ph[0], ph[1], ph[2], ph[3]);
            *(float4*)&Pl[pr][pc] = make_float4(pl[0], pl[1], pl[2], pl[3]);
        }
        // V tile, transposed into smem
        {
            int jj = j0 + vj;
            float4 vv = (jj < N) ? *(const float4*)(V + (size_t)jj*2304 + vd) : z4;
            float vvv[4] = {vv.x, vv.y, vv.z, vv.w};
            #pragma unroll
            for (int q = 0; q < 4; q++) {
                uint32_t hh = f2tf(vvv[q]);
                float hf = __uint_as_float(hh);
                Vh[vd + q][vj] = hf;
                Vl[vd + q][vj] = vvv[q] - hf;
            }
        }
        __syncthreads();
        #pragma unroll
        for (int ks = 0; ks < 2; ks++) {
            int k = ks*8 + tig;
            uint32_t bhf[2][2], blf[2][2];
            #pragma unroll
            for (int nt = 0; nt < 2; nt++) {
                int n = wn*16 + nt*8 + g;
                bhf[nt][0] = __float_as_uint(Vh[n][k]);
                bhf[nt][1] = __float_as_uint(Vh[n][k+4]);
                blf[nt][0] = __float_as_uint(Vl[n][k]);
                blf[nt][1] = __float_as_uint(Vl[n][k+4]);
            }
            #pragma unroll
            for (int mt = 0; mt < 2; mt++) {
                int r = wm*32 + mt*16 + g;
                uint32_t ah[4], al[4];
                ah[0] = __float_as_uint(Ph[r][k]);
                ah[1] = __float_as_uint(Ph[r+8][k]);
                ah[2] = __float_as_uint(Ph[r][k+4]);
                ah[3] = __float_as_uint(Ph[r+8][k+4]);
                al[0] = __float_as_uint(Pl[r][k]);
                al[1] = __float_as_uint(Pl[r+8][k]);
                al[2] = __float_as_uint(Pl[r][k+4]);
                al[3] = __float_as_uint(Pl[r+8][k+4]);
                #pragma unroll
                for (int nt = 0; nt < 2; nt++) {
                    mma_tf32(acc[mt][nt], al, bhf[nt]);
                    mma_tf32(acc[mt][nt], ah, blf[nt]);
                    mma_tf32(acc[mt][nt], ah, bhf[nt]);
                }
            }
        }
        __syncthreads();
    }

    #pragma unroll
    for (int mt = 0; mt < 2; mt++) {
        #pragma unroll
        for (int nt = 0; nt < 2; nt++) {
            int gc0 = wn*16 + nt*8 + 2*tig;
            #pragma unroll
            for (int half = 0; half < 2; half++) {
                int gr = row0 + wm*32 + mt*16 + g + half*8;
                if (gr >= N) continue;
                #pragma unroll
                for (int j = 0; j < 2; j++) {
                    C[(size_t)gr*DD + gc0 + j] = acc[mt][nt][half*2 + j];
                }
            }
        }
    }
}

// ---------------- SIMT GEMM (kept for tiny shapes: N=1 predictor head, class head) -
__global__ void gemm_kernel(const float* __restrict__ A, const float* __restrict__ W,
                            const float* __restrict__ bias, const float* __restrict__ resid,
                            float* __restrict__ C, int M, int N, int K, int act)
{
    __shared__ float As[16][65];
    __shared__ float Ws[16][65];
    int tx = threadIdx.x, ty = threadIdx.y;
    int tid = ty*16 + tx;
    int row0 = blockIdx.y*64, col0 = blockIdx.x*64;
    float acc[4][4] = {};
    for (int k0 = 0; k0 < K; k0 += 16) {
        #pragma unroll
        for (int i = 0; i < 4; i++) {
            int idx = tid + i*256;
            int r = idx >> 4;
            int c = idx & 15;
            int gr = row0 + r;
            As[c][r] = (gr < M) ? A[(size_t)gr*K + k0 + c] : 0.f;
            int wr = col0 + r;
            Ws[c][r] = (wr < N) ? W[(size_t)wr*K + k0 + c] : 0.f;
        }
        __syncthreads();
        #pragma unroll
        for (int kk = 0; kk < 16; kk++) {
            float a[4], bb[4];
            #pragma unroll
            for (int i = 0; i < 4; i++) a[i] = As[kk][ty*4+i];
            #pragma unroll
            for (int j = 0; j < 4; j++) bb[j] = Ws[kk][tx*4+j];
            #pragma unroll
            for (int i = 0; i < 4; i++)
                #pragma unroll
                for (int j = 0; j < 4; j++)
                    acc[i][j] = fmaf(a[i], bb[j], acc[i][j]);
        }
        __syncthreads();
    }
    #pragma unroll
    for (int i = 0; i < 4; i++) {
        int gr = row0 + ty*4 + i;
        if (gr >= M) continue;
        #pragma unroll
        for (int j = 0; j < 4; j++) {
            int gc = col0 + tx*4 + j;
            if (gc >= N) continue;
            float v = acc[i][j] + bias[gc];
            if (act == 1) v = gelu_f(v);
            if (resid) v += resid[(size_t)gr*N + gc];
            C[(size_t)gr*N + gc] = v;
        }
    }
}

// ---------------- LayerNorm (row mapping supports t[:,1:] and cls-only) ---------
__global__ void ln_kernel(const float* __restrict__ src, float* __restrict__ dst,
                          const float* __restrict__ gamma, const float* __restrict__ beta,
                          int n_src_tokens, int toks_out, int tok_off)
{
    int r = blockIdx.x;
    int b = r / toks_out;
    int n = r % toks_out + tok_off;
    const float* x = src + ((size_t)b*n_src_tokens + n)*DD;
    float* y = dst + (size_t)r*DD;
    int tid = threadIdx.x;                 // 256
    float v[3];
    float s = 0.f, s2 = 0.f;
    #pragma unroll
    for (int i = 0; i < 3; i++) { v[i] = x[tid + i*256]; s += v[i]; s2 += v[i]*v[i]; }
    __shared__ float sh1[8], sh2[8];
    #pragma unroll
    for (int o = 16; o > 0; o >>= 1) {
        s  += __shfl_xor_sync(0xffffffffu, s,  o);
        s2 += __shfl_xor_sync(0xffffffffu, s2, o);
    }
    if ((tid & 31) == 0) { sh1[tid>>5] = s; sh2[tid>>5] = s2; }
    __syncthreads();
    float ts = 0.f, ts2 = 0.f;
    #pragma unroll
    for (int w = 0; w < 8; w++) { ts += sh1[w]; ts2 += sh2[w]; }
    float mean = ts * (1.f/768.f);
    float var  = ts2 * (1.f/768.f) - mean*mean;
    float rstd = rsqrtf(var + 1e-6f);
    #pragma unroll
    for (int i = 0; i < 3; i++) {
        int c = tid + i*256;
        y[c] = (v[i] - mean) * rstd * gamma[c] + beta[c];
    }
}

// ---------------- predictor helpers ----------------
__global__ void globmean_kernel(const float* __restrict__ hidden, float* __restrict__ glob, int L)
{
    int b = blockIdx.x;
    int c = threadIdx.x;                   // 384
    float s = 0.f;
    for (int l = 0; l < L; l++) s += hidden[((size_t)b*L + l)*DD + 384 + c];
    glob[b*384 + c] = s / (float)L;
}

__global__ void combine_kernel(const float* __restrict__ hidden, const float* __restrict__ glob,
                               float* __restrict__ h2, int L)
{
    int i = blockIdx.x * blockDim.x + threadIdx.x;
    int total = BB*L*DD;
    if (i >= total) return;
    int c = i % DD;
    int r = i / DD;
    int b = r / L;
    h2[i] = (c < 384) ? hidden[i] : glob[b*384 + (c - 384)];
}

// exact jax top_k order via rank counting (score desc, index asc tie-break).
__global__ void topk_kernel(const float* __restrict__ score, int* __restrict__ idx, int L, int k)
{
    int b = blockIdx.x;
    __shared__ float s[LMAX];
    int t = threadIdx.x;                   // 256
    for (int j = t; j < L; j += blockDim.x) s[j] = score[b*L + j];
    __syncthreads();
    if (t < L) {
        float my = s[t];
        int rank = 0;
        for (int j = 0; j < L; j++) {
            float v = s[j];
            rank += (v > my) || (v == my && j < t);
        }
        if (rank < k) idx[b*LMAX + rank] = t;
    }
}

__global__ void gather_kernel(const float* __restrict__ tin, const int* __restrict__ idx,
                              float* __restrict__ tout, int Nin, int Nout)
{
    int i = blockIdx.x * blockDim.x + threadIdx.x;
    int total = BB*Nout*DD;
    if (i >= total) return;
    int c = i % DD;
    int r = i / DD;
    int b = r / Nout;
    int j = r % Nout;
    int n = (j == 0) ? 0 : (1 + idx[b*LMAX + (j - 1)]);
    tout[i] = tin[((size_t)b*Nin + n)*DD + c];
}

// ---------------- host orchestration ----------------
static inline void launch_gemm_tc(const float* A, const float* W, const float* bias,
                                  const float* resid, float* C, int M, int N, int K, int act)
{
    dim3 grid((N + 127) / 128, (M + 127) / 128);
    gemm_tc_kernel<<<grid, 256>>>(A, W, bias, resid, C, M, N, K, act);
}

static inline void launch_gemm(const float* A, const float* W, const float* bias,
                               const float* resid, float* C, int M, int N, int K, int act)
{
    dim3 grid((N + 63) / 64, (M + 63) / 64);
    dim3 block(16, 16);
    gemm_kernel<<<grid, block>>>(A, W, bias, resid, C, M, N, K, act);
}

extern "C" void kernel_launch(void* const* d_in, const int* in_sizes, int n_in,
                              void* d_out, int out_size)
{
    const float* x       = (const float*)d_in[0];
    const float* patch_w = (const float*)d_in[1];
    const float* patch_b = (const float*)d_in[2];
    const float* cls_tok = (const float*)d_in[3];
    const float* pos     = (const float*)d_in[4];
    const float* ln1_g   = (const float*)d_in[5];
    const float* ln1_b   = (const float*)d_in[6];
    const float* qkv_w   = (const float*)d_in[7];
    const float* qkv_b   = (const float*)d_in[8];
    const float* proj_w  = (const float*)d_in[9];
    const float* proj_b  = (const float*)d_in[10];
    const float* ln2_g   = (const float*)d_in[11];
    const float* ln2_b   = (const float*)d_in[12];
    const float* fc1_w   = (const float*)d_in[13];
    const float* fc1_b   = (const float*)d_in[14];
    const float* fc2_w   = (const float*)d_in[15];
    const float* fc2_b   = (const float*)d_in[16];
    const float* pln_g   = (const float*)d_in[17];
    const float* pln_b   = (const float*)d_in[18];
    const float* pin_w   = (const float*)d_in[19];
    const float* pin_b   = (const float*)d_in[20];
    const float* pw1     = (const float*)d_in[21];
    const float* pb1     = (const float*)d_in[22];
    const float* pw2     = (const float*)d_in[23];
    const float* pb2     = (const float*)d_in[24];
    const float* pw3     = (const float*)d_in[25];
    const float* pb3     = (const float*)d_in[26];
    const float* norm_g  = (const float*)d_in[27];
    const float* norm_b  = (const float*)d_in[28];
    const float* head_w  = (const float*)d_in[29];
    const float* head_b  = (const float*)d_in[30];
    (void)in_sizes; (void)n_in; (void)out_size;

    void* p;
    cudaGetSymbolAddress(&p, g_t0);    float* t0    = (float*)p;
    cudaGetSymbolAddress(&p, g_t1);    float* t1    = (float*)p;
    cudaGetSymbolAddress(&p, g_ln);    float* lnb   = (float*)p;
    cudaGetSymbolAddress(&p, g_qkv);   float* qkvb  = (float*)p;
    cudaGetSymbolAddress(&p, g_ao);    float* ao    = (float*)p;
    cudaGetSymbolAddress(&p, g_mlp);   float* mlpb  = (float*)p;
    cudaGetSymbolAddress(&p, g_pa);    float* pa    = (float*)p;
    cudaGetSymbolAddress(&p, g_pb);    float* pbuf  = (float*)p;
    cudaGetSymbolAddress(&p, g_glob);  float* glob  = (float*)p;
    cudaGetSymbolAddress(&p, g_score); float* score = (float*)p;
    cudaGetSymbolAddress(&p, g_idx);   int*   gidx  = (int*)p;
    cudaGetSymbolAddress(&p, g_cls);   float* clsb  = (float*)p;
    cudaGetSymbolAddress(&p, g_att);   float* attb  = (float*)p;

    // patch embedding
    { int total = BB*LMAX*DD; im2col_kernel<<<(total + 255)/256, 256>>>(x, pa); }
    launch_gemm_tc(pa, patch_w, patch_b, nullptr, pbuf, BB*LMAX, DD, DD, 0);
    { int total = BB*NMAX*DD; assemble_kernel<<<(total + 255)/256, 256>>>(pbuf, cls_tok, pos, t0); }

    float* ta = t0;
    float* tb = t1;
    int N = NMAX;
    const int kkeep[3] = {138, 97, 68};

    for (int i = 0; i < 12; i++) {
        int s = (i == 3) ? 0 : (i == 6) ? 1 : (i == 9) ? 2 : -1;
        if (s >= 0) {
            int L = N - 1;
            int M = BB * L;
            ln_kernel<<<M, 256>>>(ta, pa, pln_g + s*DD, pln_b + s*DD, N, L, 1);
            launch_gemm_tc(pa, pin_w + (size_t)s*DD*DD, pin_b + s*DD, nullptr, pbuf, M, DD, DD, 1);
            globmean_kernel<<<BB, 384>>>(pbuf, glob, L);
            { int total = M*DD; combine_kernel<<<(total + 255)/256, 256>>>(pbuf, glob, pa, L); }
            launch_gemm_tc(pa,   pw1 + (size_t)s*384*DD,  pb1 + s*384, nullptr, pbuf,  M, 384, DD,  1);
            launch_gemm_tc(pbuf, pw2 + (size_t)s*192*384, pb2 + s*192, nullptr, pa,    M, 192, 384, 1);
            launch_gemm(pa,   pw3 + (size_t)s*192,     pb3 + s,     nullptr, score, M, 1,   192, 0);
            topk_kernel<<<BB, 256>>>(score, gidx, L, kkeep[s]);
            int Nn = kkeep[s] + 1;
            { int total = BB*Nn*DD; gather_kernel<<<(total + 255)/256, 256>>>(ta, gidx, tb, N, Nn); }
            float* tmp = ta; ta = tb; tb = tmp;
            N = Nn;
        }
        int M = BB * N;
        int ntile = (N + 63) / 64;
        ln_kernel<<<M, 256>>>(ta, lnb, ln1_g + i*DD, ln1_b + i*DD, N, N, 0);
        launch_gemm_tc(lnb, qkv_w + (size_t)i*2304*DD, qkv_b + i*2304, nullptr, qkvb, M, 2304, DD, 0);
        {
            dim3 gqk(ntile, ntile, BB*NHD);
            attn_qk_kernel<<<gqk, 256>>>(qkvb, attb, N);
            int rows = BB*NHD*N;
            attn_softmax_kernel<<<(rows + 3)/4, 128>>>(attb, N, rows);
            dim3 gpv(1, ntile, BB*NHD);
            attn_pv_kernel<<<gpv, 256>>>(attb, qkvb, ao, N);
        }
        launch_gemm_tc(ao, proj_w + (size_t)i*DD*DD, proj_b + i*DD, ta, tb, M, DD, DD, 0);
        ln_kernel<<<M, 256>>>(tb, lnb, ln2_g + i*DD, ln2_b + i*DD, N, N, 0);
        launch_gemm_tc(lnb, fc1_w + (size_t)i*3072*DD, fc1_b + i*3072, nullptr, mlpb, M, 3072, DD, 1);
        launch_gemm_tc(mlpb, fc2_w + (size_t)i*DD*3072, fc2_b + i*DD, tb, ta, M, DD, 3072, 0);
    }

    // final LN on cls token + classification head
    ln_kernel<<<BB, 256>>>(ta, clsb, norm_g, norm_b, N, 1, 0);
    launch_gemm(clsb, head_w, head_b, nullptr, (float*)d_out, BB, 1000, DD, 0);
}

// round 9
// speedup vs baseline: 4.3546x; 1.5901x over previous
#include <cuda_runtime.h>
#include <cuda_bf16.h>
#include <math.h>
#include <stdint.h>

#define BB   32
#define DD   768
#define NHD  12
#define HD   64
#define NMAX 197
#define LMAX 196
#define ATTN_SCALE 0.125f

// ---------------- scratch (device globals; no allocation allowed) ----------------
__device__ float g_t0[BB*NMAX*DD];
__device__ float g_t1[BB*NMAX*DD];
__device__ float g_ln[BB*NMAX*DD];
__device__ float g_qkv[BB*NMAX*2304];
__device__ float g_ao[BB*NMAX*DD];
__device__ float g_mlp[BB*NMAX*3072];
__device__ float g_pa[BB*LMAX*DD];
__device__ float g_pb[BB*LMAX*DD];
__device__ float g_glob[BB*384];
__device__ float g_score[BB*LMAX];
__device__ int   g_idx[BB*LMAX];
__device__ float g_cls[BB*DD];
__device__ float g_att[(size_t)BB*NHD*NMAX*NMAX];   // attention scores/probs (~60 MB)

__device__ __forceinline__ float gelu_f(float x) {
    return 0.5f * x * (1.f + erff(x * 0.70710678118654752440f));
}

// ---------------- im2col for patch embedding ----------------
__global__ void im2col_kernel(const float* __restrict__ x, float* __restrict__ p) {
    int i = blockIdx.x * blockDim.x + threadIdx.x;
    const int total = BB*LMAX*DD;
    if (i >= total) return;
    int c = i % DD;
    int r = i / DD;
    int b = r / LMAX;
    int l = r % LMAX;
    int gy = l / 14, gx = l % 14;
    int ch = c / 256, rem = c % 256, py = rem / 16, px = rem % 16;
    p[i] = x[(((size_t)b*3 + ch)*224 + gy*16 + py)*224 + gx*16 + px];
}

// assemble t = [cls | patches] + pos
__global__ void assemble_kernel(const float* __restrict__ pe, const float* __restrict__ cls,
                                const float* __restrict__ pos, float* __restrict__ t) {
    int i = blockIdx.x * blockDim.x + threadIdx.x;
    const int total = BB*NMAX*DD;
    if (i >= total) return;
    int d = i % DD;
    int n = (i / DD) % NMAX;
    int b = i / (DD*NMAX);
    float v = (n == 0) ? cls[d] : pe[((size_t)b*LMAX + (n-1))*DD + d];
    t[i] = v + pos[n*DD + d];
}

// =====================================================================
// mma helpers
// =====================================================================
#define SK 20   // smem row stride: all 32 banks hit once per frag load

__device__ __forceinline__ uint32_t f2tf(float f) {
    uint32_t u;
    asm("cvt.rna.tf32.f32 %0, %1;" : "=r"(u) : "f"(f));
    return u;
}

__device__ __forceinline__ void mma_tf32(float d[4], const uint32_t a[4], const uint32_t b[2]) {
    asm volatile(
        "mma.sync.aligned.m16n8k8.row.col.f32.tf32.tf32.f32 "
        "{%0,%1,%2,%3}, {%4,%5,%6,%7}, {%8,%9}, {%0,%1,%2,%3};\n"
        : "+f"(d[0]), "+f"(d[1]), "+f"(d[2]), "+f"(d[3])
        : "r"(a[0]), "r"(a[1]), "r"(a[2]), "r"(a[3]), "r"(b[0]), "r"(b[1]));
}

__device__ __forceinline__ void mma_bf16(float d[4], const uint32_t a[4], const uint32_t b[2]) {
    asm volatile(
        "mma.sync.aligned.m16n8k16.row.col.f32.bf16.bf16.f32 "
        "{%0,%1,%2,%3}, {%4,%5,%6,%7}, {%8,%9}, {%0,%1,%2,%3};\n"
        : "+f"(d[0]), "+f"(d[1]), "+f"(d[2]), "+f"(d[3])
        : "r"(a[0]), "r"(a[1]), "r"(a[2]), "r"(a[3]), "r"(b[0]), "r"(b[1]));
}

// split two floats into packed bf16 hi pair + lo pair
__device__ __forceinline__ void split2_bf16(float v0, float v1, uint32_t& hi, uint32_t& lo) {
    __nv_bfloat16 h0 = __float2bfloat16(v0);
    __nv_bfloat16 h1 = __float2bfloat16(v1);
    float r0 = v0 - __bfloat162float(h0);
    float r1 = v1 - __bfloat162float(h1);
    __nv_bfloat16 l0 = __float2bfloat16(r0);
    __nv_bfloat16 l1 = __float2bfloat16(r1);
    hi = (uint32_t)__bfloat16_as_ushort(h0) | ((uint32_t)__bfloat16_as_ushort(h1) << 16);
    lo = (uint32_t)__bfloat16_as_ushort(l0) | ((uint32_t)__bfloat16_as_ushort(l1) << 16);
}

// =====================================================================
// Tensor-core GEMM: C = act(A[M,K] @ W[N,K]^T + bias) (+resid)
// 3xBF16 (hi/lo split, m16n8k16) — 2x MACs/instr vs tf32 k8.
// 128x128x16 CTA tile, 256 threads, warp grid 2x4, warp tile 64x32.
// =====================================================================
__global__ __launch_bounds__(256)
void gemm_tc_kernel(const float* __restrict__ A, const float* __restrict__ W,
                    const float* __restrict__ bias, const float* __restrict__ resid,
                    float* __restrict__ C, int M, int N, int K, int act)
{
    // packed bf16 pairs along k: 8 words per 16-wide k tile
    __shared__ __align__(16) uint32_t Ah[128][SK];
    __shared__ __align__(16) uint32_t Al[128][SK];
    __shared__ __align__(16) uint32_t Bh[128][SK];
    __shared__ __align__(16) uint32_t Bl[128][SK];

    int tid = threadIdx.x;
    int lane = tid & 31, w = tid >> 5;
    int wm = w >> 2, wn = w & 3;          // warp grid 2x4
    int g = lane >> 2, tig = lane & 3;    // mma quad coords
    int row0 = blockIdx.y * 128, col0 = blockIdx.x * 128;

    float acc[4][4][4];
    #pragma unroll
    for (int i = 0; i < 4; i++)
        #pragma unroll
        for (int j = 0; j < 4; j++)
            #pragma unroll
            for (int q = 0; q < 4; q++) acc[i][j][q] = 0.f;

    int ldr = tid >> 2;          // 0..63
    int ldc = (tid & 3) * 4;     // float col: 0,4,8,12
    int wc  = (tid & 3) * 2;     // packed word col: 0,2,4,6

    const float4 z4 = make_float4(0.f, 0.f, 0.f, 0.f);
    float4 pa[2], pb[2];

    // initial prefetch (k0 = 0)
    #pragma unroll
    for (int i = 0; i < 2; i++) {
        int gr = row0 + ldr + i*64;
        pa[i] = (gr < M) ? *(const float4*)(A + (size_t)gr*K + ldc) : z4;
        int wr = col0 + ldr + i*64;
        pb[i] = (wr < N) ? *(const float4*)(W + (size_t)wr*K + ldc) : z4;
    }

    int ktiles = K >> 4;
    for (int kt = 0; kt < ktiles; kt++) {
        // split into bf16 hi/lo pairs and store to smem
        #pragma unroll
        for (int i = 0; i < 2; i++) {
            int r = ldr + i*64;
            uint32_t h0, l0, h1, l1;
            split2_bf16(pa[i].x, pa[i].y, h0, l0);
            split2_bf16(pa[i].z, pa[i].w, h1, l1);
            Ah[r][wc] = h0; Ah[r][wc+1] = h1;
            Al[r][wc] = l0; Al[r][wc+1] = l1;
            split2_bf16(pb[i].x, pb[i].y, h0, l0);
            split2_bf16(pb[i].z, pb[i].w, h1, l1);
            Bh[r][wc] = h0; Bh[r][wc+1] = h1;
            Bl[r][wc] = l0; Bl[r][wc+1] = l1;
        }
        __syncthreads();

        // prefetch next tile (overlaps with mma below)
        if (kt + 1 < ktiles) {
            int k0 = (kt + 1) << 4;
            #pragma unroll
            for (int i = 0; i < 2; i++) {
                int gr = row0 + ldr + i*64;
                pa[i] = (gr < M) ? *(const float4*)(A + (size_t)gr*K + k0 + ldc) : z4;
                int wr = col0 + ldr + i*64;
                pb[i] = (wr < N) ? *(const float4*)(W + (size_t)wr*K + k0 + ldc) : z4;
            }
        }

        // compute: one m16n8k16 covers the whole 16-wide k tile
        {
            uint32_t bhf[4][2], blf[4][2];
            #pragma unroll
            for (int nt = 0; nt < 4; nt++) {
                int n = wn*32 + nt*8 + g;
                bhf[nt][0] = Bh[n][tig];
                bhf[nt][1] = Bh[n][tig+4];
                blf[nt][0] = Bl[n][tig];
                blf[nt][1] = Bl[n][tig+4];
            }
            #pragma unroll
            for (int mt = 0; mt < 4; mt++) {
                int r = wm*64 + mt*16 + g;
                uint32_t ah[4], al[4];
                ah[0] = Ah[r][tig];
                ah[1] = Ah[r+8][tig];
                ah[2] = Ah[r][tig+4];
                ah[3] = Ah[r+8][tig+4];
                al[0] = Al[r][tig];
                al[1] = Al[r+8][tig];
                al[2] = Al[r][tig+4];
                al[3] = Al[r+8][tig+4];
                #pragma unroll
                for (int nt = 0; nt < 4; nt++) {
                    mma_bf16(acc[mt][nt], al, bhf[nt]);   // lo*hi
                    mma_bf16(acc[mt][nt], ah, blf[nt]);   // hi*lo
                    mma_bf16(acc[mt][nt], ah, bhf[nt]);   // hi*hi
                }
            }
        }
        __syncthreads();
    }

    // epilogue
    #pragma unroll
    for (int mt = 0; mt < 4; mt++) {
        #pragma unroll
        for (int nt = 0; nt < 4; nt++) {
            int gc0 = col0 + wn*32 + nt*8 + 2*tig;
            #pragma unroll
            for (int half = 0; half < 2; half++) {
                int gr = row0 + wm*64 + mt*16 + g + half*8;
                if (gr >= M) continue;
                #pragma unroll
                for (int j = 0; j < 2; j++) {
                    int gc = gc0 + j;
                    if (gc >= N) continue;
                    float v = acc[mt][nt][half*2 + j] + bias[gc];
                    if (act == 1) v = gelu_f(v);
                    if (resid) v += resid[(size_t)gr*N + gc];
                    C[(size_t)gr*N + gc] = v;
                }
            }
        }
    }
}

// =====================================================================
// Batched attention, stage 1: scores = Q @ K^T per (b,h).
// 64x64 tile over (i,j), K=64. blockIdx.z = b*NHD+h. 3xTF32.
// =====================================================================
__global__ __launch_bounds__(256)
void attn_qk_kernel(const float* __restrict__ qkv, float* __restrict__ att, int N)
{
    __shared__ __align__(16) float Ah[64][SK];
    __shared__ __align__(16) float Al[64][SK];
    __shared__ __align__(16) float Bh[64][SK];
    __shared__ __align__(16) float Bl[64][SK];

    int tid = threadIdx.x;
    int lane = tid & 31, w = tid >> 5;
    int wm = w >> 2, wn = w & 3;          // 2x4 warps -> warp tile 32x16
    int g = lane >> 2, tig = lane & 3;
    int bh = blockIdx.z;
    int b = bh / NHD, h = bh % NHD;
    const float* Q  = qkv + (size_t)b*N*2304 + h*HD;
    const float* Kp = qkv + (size_t)b*N*2304 + 768 + h*HD;
    float* C = att + (size_t)bh*N*N;
    int row0 = blockIdx.y * 64, col0 = blockIdx.x * 64;

    float acc[2][2][4];
    #pragma unroll
    for (int i = 0; i < 2; i++)
        #pragma unroll
        for (int j = 0; j < 2; j++)
            #pragma unroll
            for (int q = 0; q < 4; q++) acc[i][j][q] = 0.f;

    int ldr = tid >> 2;           // 0..63
    int ldc = (tid & 3) * 4;      // 0,4,8,12
    const float4 z4 = make_float4(0.f, 0.f, 0.f, 0.f);

    #pragma unroll
    for (int kt = 0; kt < 4; kt++) {
        int k0 = kt * 16;
        {
            int gr = row0 + ldr;
            float4 va = (gr < N) ? *(const float4*)(Q + (size_t)gr*2304 + k0 + ldc) : z4;
            int wr = col0 + ldr;
            float4 vb = (wr < N) ? *(const float4*)(Kp + (size_t)wr*2304 + k0 + ldc) : z4;
            float av[4] = {va.x, va.y, va.z, va.w};
            float bv[4] = {vb.x, vb.y, vb.z, vb.w};
            float4 ah4, al4, bh4, bl4;
            float* ahp = &ah4.x; float* alp = &al4.x;
            float* bhp = &bh4.x; float* blp = &bl4.x;
            #pragma unroll
            for (int j = 0; j < 4; j++) {
                uint32_t hh = f2tf(av[j]);
                ahp[j] = __uint_as_float(hh);
                alp[j] = av[j] - ahp[j];
                uint32_t hb = f2tf(bv[j]);
                bhp[j] = __uint_as_float(hb);
                blp[j] = bv[j] - bhp[j];
            }
            *(float4*)&Ah[ldr][ldc] = ah4;
            *(float4*)&Al[ldr][ldc] = al4;
            *(float4*)&Bh[ldr][ldc] = bh4;
            *(float4*)&Bl[ldr][ldc] = bl4;
        }
        __syncthreads();
        #pragma unroll
        for (int ks = 0; ks < 2; ks++) {
            int k = ks*8 + tig;
            uint32_t bhf[2][2], blf[2][2];
            #pragma unroll
            for (int nt = 0; nt < 2; nt++) {
                int n = wn*16 + nt*8 + g;
                bhf[nt][0] = __float_as_uint(Bh[n][k]);
                bhf[nt][1] = __float_as_uint(Bh[n][k+4]);
                blf[nt][0] = __float_as_uint(Bl[n][k]);
                blf[nt][1] = __float_as_uint(Bl[n][k+4]);
            }
            #pragma unroll
            for (int mt = 0; mt < 2; mt++) {
                int r = wm*32 + mt*16 + g;
                uint32_t ah[4], al[4];
                ah[0] = __float_as_uint(Ah[r][k]);
                ah[1] = __float_as_uint(Ah[r+8][k]);
                ah[2] = __float_as_uint(Ah[r][k+4]);
                ah[3] = __float_as_uint(Ah[r+8][k+4]);
                al[0] = __float_as_uint(Al[r][k]);
                al[1] = __float_as_uint(Al[r+8][k]);
                al[2] = __float_as_uint(Al[r][k+4]);
                al[3] = __float_as_uint(Al[r+8][k+4]);
                #pragma unroll
                for (int nt = 0; nt < 2; nt++) {
                    mma_tf32(acc[mt][nt], al, bhf[nt]);
                    mma_tf32(acc[mt][nt], ah, blf[nt]);
                    mma_tf32(acc[mt][nt], ah, bhf[nt]);
                }
            }
        }
        __syncthreads();
    }

    #pragma unroll
    for (int mt = 0; mt < 2; mt++) {
        #pragma unroll
        for (int nt = 0; nt < 2; nt++) {
            int gc0 = col0 + wn*16 + nt*8 + 2*tig;
            #pragma unroll
            for (int half = 0; half < 2; half++) {
                int gr = row0 + wm*32 + mt*16 + g + half*8;
                if (gr >= N) continue;
                #pragma unroll
                for (int j = 0; j < 2; j++) {
                    int gc = gc0 + j;
                    if (gc < N) C[(size_t)gr*N + gc] = acc[mt][nt][half*2 + j];
                }
            }
        }
    }
}

// =====================================================================
// Batched attention, stage 2: in-place row softmax of scaled scores.
// =====================================================================
__global__ void attn_softmax_kernel(float* __restrict__ att, int N, int rows)
{
    int row = blockIdx.x * 4 + (threadIdx.x >> 5);
    if (row >= rows) return;
    int lane = threadIdx.x & 31;
    float* p = att + (size_t)row * N;
    float v[7];
    int cnt = 0;
    float m = -1e30f;
    for (int j = lane; j < N; j += 32) { float s = p[j]; v[cnt++] = s; m = fmaxf(m, s); }
    #pragma unroll
    for (int o = 16; o > 0; o >>= 1) m = fmaxf(m, __shfl_xor_sync(0xffffffffu, m, o));
    float sum = 0.f;
    #pragma unroll
    for (int q = 0; q < 7; q++) {
        if (q < cnt) { v[q] = expf((v[q] - m) * ATTN_SCALE); sum += v[q]; }
    }
    #pragma unroll
    for (int o = 16; o > 0; o >>= 1) sum += __shfl_xor_sync(0xffffffffu, sum, o);
    float inv = 1.f / sum;
    cnt = 0;
    for (int j = lane; j < N; j += 32) p[j] = v[cnt++] * inv;
}

// =====================================================================
// Batched attention, stage 3: O = P @ V per (b,h).
// =====================================================================
__global__ __launch_bounds__(256)
void attn_pv_kernel(const float* __restrict__ att, const float* __restrict__ qkv,
                    float* __restrict__ o, int N)
{
    __shared__ __align__(16) float Ph[64][SK];
    __shared__ __align__(16) float Pl[64][SK];
    __shared__ __align__(16) float Vh[64][SK];   // [d][j]
    __shared__ __align__(16) float Vl[64][SK];

    int tid = threadIdx.x;
    int lane = tid & 31, w = tid >> 5;
    int wm = w >> 2, wn = w & 3;
    int g = lane >> 2, tig = lane & 3;
    int bh = blockIdx.z;
    int b = bh / NHD, h = bh % NHD;
    const float* P = att + (size_t)bh*N*N;
    const float* V = qkv + (size_t)b*N*2304 + 1536 + h*HD;
    float* C = o + (size_t)b*N*DD + h*HD;
    int row0 = blockIdx.y * 64;

    float acc[2][2][4];
    #pragma unroll
    for (int i = 0; i < 2; i++)
        #pragma unroll
        for (int j = 0; j < 2; j++)
            #pragma unroll
            for (int q = 0; q < 4; q++) acc[i][j][q] = 0.f;

    const float4 z4 = make_float4(0.f, 0.f, 0.f, 0.f);
    int pr = tid >> 2;            // P row (query) 0..63
    int pc = (tid & 3) * 4;       // P col base within tile
    int vj = tid >> 4;            // V row (key) within tile 0..15
    int vd = (tid & 15) * 4;      // V col base 0..60

    int ktiles = (N + 15) >> 4;
    for (int kt = 0; kt < ktiles; kt++) {
        int j0 = kt * 16;
        // P tile (scalar loads: row stride N is odd)
        {
            int gi = row0 + pr;
            float pv[4], ph[4], pl[4];
            #pragma unroll
            for (int q = 0; q < 4; q++) {
                int jj = j0 + pc + q;
                pv[q] = (gi < N && jj < N) ? P[(size_t)gi*N + jj] : 0.f;
                uint32_t hh = f2tf(pv[q]);
                ph[q] = __uint_as_float(hh);
                pl[q] = pv[q] - ph[q];
            }
            *(float4*)&Ph[pr][pc] = make_float4(ph[0], ph[1], ph[2], ph[3]);
            *(float4*)&Pl[pr][pc] = make_float4(pl[0], pl[1], pl[2], pl[3]);
        }
        // V tile, transposed into smem
        {
            int jj = j0 + vj;
            float4 vv = (jj < N) ? *(const float4*)(V + (size_t)jj*2304 + vd) : z4;
            float vvv[4] = {vv.x, vv.y, vv.z, vv.w};
            #pragma unroll
            for (int q = 0; q < 4; q++) {
                uint32_t hh = f2tf(vvv[q]);
                float hf = __uint_as_float(hh);
                Vh[vd + q][vj] = hf;
                Vl[vd + q][vj] = vvv[q] - hf;
            }
        }
        __syncthreads();
        #pragma unroll
        for (int ks = 0; ks < 2; ks++) {
            int k = ks*8 + tig;
            uint32_t bhf[2][2], blf[2][2];
            #pragma unroll
            for (int nt = 0; nt < 2; nt++) {
                int n = wn*16 + nt*8 + g;
                bhf[nt][0] = __float_as_uint(Vh[n][k]);
                bhf[nt][1] = __float_as_uint(Vh[n][k+4]);
                blf[nt][0] = __float_as_uint(Vl[n][k]);
                blf[nt][1] = __float_as_uint(Vl[n][k+4]);
            }
            #pragma unroll
            for (int mt = 0; mt < 2; mt++) {
                int r = wm*32 + mt*16 + g;
                uint32_t ah[4], al[4];
                ah[0] = __float_as_uint(Ph[r][k]);
                ah[1] = __float_as_uint(Ph[r+8][k]);
                ah[2] = __float_as_uint(Ph[r][k+4]);
                ah[3] = __float_as_uint(Ph[r+8][k+4]);
                al[0] = __float_as_uint(Pl[r][k]);
                al[1] = __float_as_uint(Pl[r+8][k]);
                al[2] = __float_as_uint(Pl[r][k+4]);
                al[3] = __float_as_uint(Pl[r+8][k+4]);
                #pragma unroll
                for (int nt = 0; nt < 2; nt++) {
                    mma_tf32(acc[mt][nt], al, bhf[nt]);
                    mma_tf32(acc[mt][nt], ah, blf[nt]);
                    mma_tf32(acc[mt][nt], ah, bhf[nt]);
                }
            }
        }
        __syncthreads();
    }

    #pragma unroll
    for (int mt = 0; mt < 2; mt++) {
        #pragma unroll
        for (int nt = 0; nt < 2; nt++) {
            int gc0 = wn*16 + nt*8 + 2*tig;
            #pragma unroll
            for (int half = 0; half < 2; half++) {
                int gr = row0 + wm*32 + mt*16 + g + half*8;
                if (gr >= N) continue;
                #pragma unroll
                for (int j = 0; j < 2; j++) {
                    C[(size_t)gr*DD + gc0 + j] = acc[mt][nt][half*2 + j];
                }
            }
        }
    }
}

// ---------------- SIMT GEMM (kept for tiny shapes: N=1 predictor head, class head) -
__global__ void gemm_kernel(const float* __restrict__ A, const float* __restrict__ W,
                            const float* __restrict__ bias, const float* __restrict__ resid,
                            float* __restrict__ C, int M, int N, int K, int act)
{
    __shared__ float As[16][65];
    __shared__ float Ws[16][65];
    int tx = threadIdx.x, ty = threadIdx.y;
    int tid = ty*16 + tx;
    int row0 = blockIdx.y*64, col0 = blockIdx.x*64;
    float acc[4][4] = {};
    for (int k0 = 0; k0 < K; k0 += 16) {
        #pragma unroll
        for (int i = 0; i < 4; i++) {
            int idx = tid + i*256;
            int r = idx >> 4;
            int c = idx & 15;
            int gr = row0 + r;
            As[c][r] = (gr < M) ? A[(size_t)gr*K + k0 + c] : 0.f;
            int wr = col0 + r;
            Ws[c][r] = (wr < N) ? W[(size_t)wr*K + k0 + c] : 0.f;
        }
        __syncthreads();
        #pragma unroll
        for (int kk = 0; kk < 16; kk++) {
            float a[4], bb[4];
            #pragma unroll
            for (int i = 0; i < 4; i++) a[i] = As[kk][ty*4+i];
            #pragma unroll
            for (int j = 0; j < 4; j++) bb[j] = Ws[kk][tx*4+j];
            #pragma unroll
            for (int i = 0; i < 4; i++)
                #pragma unroll
                for (int j = 0; j < 4; j++)
                    acc[i][j] = fmaf(a[i], bb[j], acc[i][j]);
        }
        __syncthreads();
    }
    #pragma unroll
    for (int i = 0; i < 4; i++) {
        int gr = row0 + ty*4 + i;
        if (gr >= M) continue;
        #pragma unroll
        for (int j = 0; j < 4; j++) {
            int gc = col0 + tx*4 + j;
            if (gc >= N) continue;
            float v = acc[i][j] + bias[gc];
            if (act == 1) v = gelu_f(v);
            if (resid) v += resid[(size_t)gr*N + gc];
            C[(size_t)gr*N + gc] = v;
        }
    }
}

// ---------------- LayerNorm (row mapping supports t[:,1:] and cls-only) ---------
__global__ void ln_kernel(const float* __restrict__ src, float* __restrict__ dst,
                          const float* __restrict__ gamma, const float* __restrict__ beta,
                          int n_src_tokens, int toks_out, int tok_off)
{
    int r = blockIdx.x;
    int b = r / toks_out;
    int n = r % toks_out + tok_off;
    const float* x = src + ((size_t)b*n_src_tokens + n)*DD;
    float* y = dst + (size_t)r*DD;
    int tid = threadIdx.x;                 // 256
    float v[3];
    float s = 0.f, s2 = 0.f;
    #pragma unroll
    for (int i = 0; i < 3; i++) { v[i] = x[tid + i*256]; s += v[i]; s2 += v[i]*v[i]; }
    __shared__ float sh1[8], sh2[8];
    #pragma unroll
    for (int o = 16; o > 0; o >>= 1) {
        s  += __shfl_xor_sync(0xffffffffu, s,  o);
        s2 += __shfl_xor_sync(0xffffffffu, s2, o);
    }
    if ((tid & 31) == 0) { sh1[tid>>5] = s; sh2[tid>>5] = s2; }
    __syncthreads();
    float ts = 0.f, ts2 = 0.f;
    #pragma unroll
    for (int w = 0; w < 8; w++) { ts += sh1[w]; ts2 += sh2[w]; }
    float mean = ts * (1.f/768.f);
    float var  = ts2 * (1.f/768.f) - mean*mean;
    float rstd = rsqrtf(var + 1e-6f);
    #pragma unroll
    for (int i = 0; i < 3; i++) {
        int c = tid + i*256;
        y[c] = (v[i] - mean) * rstd * gamma[c] + beta[c];
    }
}

// ---------------- predictor helpers ----------------
__global__ void globmean_kernel(const float* __restrict__ hidden, float* __restrict__ glob, int L)
{
    int b = blockIdx.x;
    int c = threadIdx.x;                   // 384
    float s = 0.f;
    for (int l = 0; l < L; l++) s += hidden[((size_t)b*L + l)*DD + 384 + c];
    glob[b*384 + c] = s / (float)L;
}

__global__ void combine_kernel(const float* __restrict__ hidden, const float* __restrict__ glob,
                               float* __restrict__ h2, int L)
{
    int i = blockIdx.x * blockDim.x + threadIdx.x;
    int total = BB*L*DD;
    if (i >= total) return;
    int c = i % DD;
    int r = i / DD;
    int b = r / L;
    h2[i] = (c < 384) ? hidden[i] : glob[b*384 + (c - 384)];
}

// exact jax top_k order via rank counting (score desc, index asc tie-break).
__global__ void topk_kernel(const float* __restrict__ score, int* __restrict__ idx, int L, int k)
{
    int b = blockIdx.x;
    __shared__ float s[LMAX];
    int t = threadIdx.x;                   // 256
    for (int j = t; j < L; j += blockDim.x) s[j] = score[b*L + j];
    __syncthreads();
    if (t < L) {
        float my = s[t];
        int rank = 0;
        for (int j = 0; j < L; j++) {
            float v = s[j];
            rank += (v > my) || (v == my && j < t);
        }
        if (rank < k) idx[b*LMAX + rank] = t;
    }
}

__global__ void gather_kernel(const float* __restrict__ tin, const int* __restrict__ idx,
                              float* __restrict__ tout, int Nin, int Nout)
{
    int i = blockIdx.x * blockDim.x + threadIdx.x;
    int total = BB*Nout*DD;
    if (i >= total) return;
    int c = i % DD;
    int r = i / DD;
    int b = r / Nout;
    int j = r % Nout;
    int n = (j == 0) ? 0 : (1 + idx[b*LMAX + (j - 1)]);
    tout[i] = tin[((size_t)b*Nin + n)*DD + c];
}

// ---------------- host orchestration ----------------
static inline void launch_gemm_tc(const float* A, const float* W, const float* bias,
                                  const float* resid, float* C, int M, int N, int K, int act)
{
    dim3 grid((N + 127) / 128, (M + 127) / 128);
    gemm_tc_kernel<<<grid, 256>>>(A, W, bias, resid, C, M, N, K, act);
}

static inline void launch_gemm(const float* A, const float* W, const float* bias,
                               const float* resid, float* C, int M, int N, int K, int act)
{
    dim3 grid((N + 63) / 64, (M + 63) / 64);
    dim3 block(16, 16);
    gemm_kernel<<<grid, block>>>(A, W, bias, resid, C, M, N, K, act);
}

extern "C" void kernel_launch(void* const* d_in, const int* in_sizes, int n_in,
                              void* d_out, int out_size)
{
    const float* x       = (const float*)d_in[0];
    const float* patch_w = (const float*)d_in[1];
    const float* patch_b = (const float*)d_in[2];
    const float* cls_tok = (const float*)d_in[3];
    const float* pos     = (const float*)d_in[4];
    const float* ln1_g   = (const float*)d_in[5];
    const float* ln1_b   = (const float*)d_in[6];
    const float* qkv_w   = (const float*)d_in[7];
    const float* qkv_b   = (const float*)d_in[8];
    const float* proj_w  = (const float*)d_in[9];
    const float* proj_b  = (const float*)d_in[10];
    const float* ln2_g   = (const float*)d_in[11];
    const float* ln2_b   = (const float*)d_in[12];
    const float* fc1_w   = (const float*)d_in[13];
    const float* fc1_b   = (const float*)d_in[14];
    const float* fc2_w   = (const float*)d_in[15];
    const float* fc2_b   = (const float*)d_in[16];
    const float* pln_g   = (const float*)d_in[17];
    const float* pln_b   = (const float*)d_in[18];
    const float* pin_w   = (const float*)d_in[19];
    const float* pin_b   = (const float*)d_in[20];
    const float* pw1     = (const float*)d_in[21];
    const float* pb1     = (const float*)d_in[22];
    const float* pw2     = (const float*)d_in[23];
    const float* pb2     = (const float*)d_in[24];
    const float* pw3     = (const float*)d_in[25];
    const float* pb3     = (const float*)d_in[26];
    const float* norm_g  = (const float*)d_in[27];
    const float* norm_b  = (const float*)d_in[28];
    const float* head_w  = (const float*)d_in[29];
    const float* head_b  = (const float*)d_in[30];
    (void)in_sizes; (void)n_in; (void)out_size;

    void* p;
    cudaGetSymbolAddress(&p, g_t0);    float* t0    = (float*)p;
    cudaGetSymbolAddress(&p, g_t1);    float* t1    = (float*)p;
    cudaGetSymbolAddress(&p, g_ln);    float* lnb   = (float*)p;
    cudaGetSymbolAddress(&p, g_qkv);   float* qkvb  = (float*)p;
    cudaGetSymbolAddress(&p, g_ao);    float* ao    = (float*)p;
    cudaGetSymbolAddress(&p, g_mlp);   float* mlpb  = (float*)p;
    cudaGetSymbolAddress(&p, g_pa);    float* pa    = (float*)p;
    cudaGetSymbolAddress(&p, g_pb);    float* pbuf  = (float*)p;
    cudaGetSymbolAddress(&p, g_glob);  float* glob  = (float*)p;
    cudaGetSymbolAddress(&p, g_score); float* score = (float*)p;
    cudaGetSymbolAddress(&p, g_idx);   int*   gidx  = (int*)p;
    cudaGetSymbolAddress(&p, g_cls);   float* clsb  = (float*)p;
    cudaGetSymbolAddress(&p, g_att);   float* attb  = (float*)p;

    // patch embedding
    { int total = BB*LMAX*DD; im2col_kernel<<<(total + 255)/256, 256>>>(x, pa); }
    launch_gemm_tc(pa, patch_w, patch_b, nullptr, pbuf, BB*LMAX, DD, DD, 0);
    { int total = BB*NMAX*DD; assemble_kernel<<<(total + 255)/256, 256>>>(pbuf, cls_tok, pos, t0); }

    float* ta = t0;
    float* tb = t1;
    int N = NMAX;
    const int kkeep[3] = {138, 97, 68};

    for (int i = 0; i < 12; i++) {
        int s = (i == 3) ? 0 : (i == 6) ? 1 : (i == 9) ? 2 : -1;
        if (s >= 0) {
            int L = N - 1;
            int M = BB * L;
            ln_kernel<<<M, 256>>>(ta, pa, pln_g + s*DD, pln_b + s*DD, N, L, 1);
            launch_gemm_tc(pa, pin_w + (size_t)s*DD*DD, pin_b + s*DD, nullptr, pbuf, M, DD, DD, 1);
            globmean_kernel<<<BB, 384>>>(pbuf, glob, L);
            { int total = M*DD; combine_kernel<<<(total + 255)/256, 256>>>(pbuf, glob, pa, L); }
            launch_gemm_tc(pa,   pw1 + (size_t)s*384*DD,  pb1 + s*384, nullptr, pbuf,  M, 384, DD,  1);
            launch_gemm_tc(pbuf, pw2 + (size_t)s*192*384, pb2 + s*192, nullptr, pa,    M, 192, 384, 1);
            launch_gemm(pa,   pw3 + (size_t)s*192,     pb3 + s,     nullptr, score, M, 1,   192, 0);
            topk_kernel<<<BB, 256>>>(score, gidx, L, kkeep[s]);
            int Nn = kkeep[s] + 1;
            { int total = BB*Nn*DD; gather_kernel<<<(total + 255)/256, 256>>>(ta, gidx, tb, N, Nn); }
            float* tmp = ta; ta = tb; tb = tmp;
            N = Nn;
        }
        int M = BB * N;
        int ntile = (N + 63) / 64;
        ln_kernel<<<M, 256>>>(ta, lnb, ln1_g + i*DD, ln1_b + i*DD, N, N, 0);
        launch_gemm_tc(lnb, qkv_w + (size_t)i*2304*DD, qkv_b + i*2304, nullptr, qkvb, M, 2304, DD, 0);
        {
            dim3 gqk(ntile, ntile, BB*NHD);
            attn_qk_kernel<<<gqk, 256>>>(qkvb, attb, N);
            int rows = BB*NHD*N;
            attn_softmax_kernel<<<(rows + 3)/4, 128>>>(attb, N, rows);
            dim3 gpv(1, ntile, BB*NHD);
            attn_pv_kernel<<<gpv, 256>>>(attb, qkvb, ao, N);
        }
        launch_gemm_tc(ao, proj_w + (size_t)i*DD*DD, proj_b + i*DD, ta, tb, M, DD, DD, 0);
        ln_kernel<<<M, 256>>>(tb, lnb, ln2_g + i*DD, ln2_b + i*DD, N, N, 0);
        launch_gemm_tc(lnb, fc1_w + (size_t)i*3072*DD, fc1_b + i*3072, nullptr, mlpb, M, 3072, DD, 1);
        launch_gemm_tc(mlpb, fc2_w + (size_t)i*DD*3072, fc2_b + i*DD, tb, ta, M, DD, 3072, 0);
    }

    // final LN on cls token + classification head
    ln_kernel<<<BB, 256>>>(ta, clsb, norm_g, norm_b, N, 1, 0);
    launch_gemm(clsb, head_w, head_b, nullptr, (float*)d_out, BB, 1000, DD, 0);
}